// round 7
// baseline (speedup 1.0000x reference)
#include <cuda_runtime.h>
#include <cuda_bf16.h>
#include <math.h>
#include <stdint.h>

// ---------------------------------------------------------------------------
// KoopmanPhiICNN encode, R7: bf16x3 mma.sync GEMMs, 3-stage cp.async pipeline
// with loads issued BEFORE compute (2 groups in flight) and merged K-segments.
// ---------------------------------------------------------------------------

#define Bsz 4096
#define Hd  832
#define Zd  256
#define BH  (Bsz*Hd)
#define HH  (Hd*Hd)
#define BZ  (Bsz*Zd)
#define NSTEPS 64

#define BM 128
#define BN 64
#define BKT 32
#define BK 16
#define NTHR 256
#define NSTAGE 3

// ---- fp32 scratch ----
#define O_SWZO 0ull
#define O_C    (O_SWZO + 1024ull)
#define O_G    (O_C + 4ull*BH)
#define O_M    (O_G + (unsigned long long)BZ)
#define O_V    (O_M + (unsigned long long)BZ)
#define TOTALF (O_V + (unsigned long long)BZ)
__device__ __align__(16) float g_buf[TOTALF];

// ---- bf16 scratch (hi/lo pairs) ----
#define SZ_WINZ  (832ull*256ull)
#define SZ_WXZ   (3ull*832ull*256ull)
#define SZ_SWZ   (3ull*(unsigned long long)HH)
#define OB_WINZ_H  0ull
#define OB_WINZ_L  (OB_WINZ_H + SZ_WINZ)
#define OB_WXZ_H   (OB_WINZ_L + SZ_WINZ)
#define OB_WXZ_L   (OB_WXZ_H + SZ_WXZ)
#define OB_SWZF_H  (OB_WXZ_L + SZ_WXZ)
#define OB_SWZF_L  (OB_SWZF_H + SZ_SWZ)
#define OB_SWZT_H  (OB_SWZF_L + SZ_SWZ)
#define OB_SWZT_L  (OB_SWZT_H + SZ_SWZ)
#define OB_WXZT_H  (OB_SWZT_L + SZ_SWZ)
#define OB_WXZT_L  (OB_WXZT_H + SZ_WXZ)
#define OB_WINZT_H (OB_WXZT_L + SZ_WXZ)
#define OB_WINZT_L (OB_WINZT_H + SZ_WINZ)
#define OB_H_H     (OB_WINZT_L + SZ_WINZ)
#define OB_H_L     (OB_H_H + 3ull*BH)
#define OB_DA_H    (OB_H_L + 3ull*BH)
#define OB_DA_L    (OB_DA_H + (unsigned long long)BH)
#define OB_DB_H    (OB_DA_L + (unsigned long long)BH)
#define OB_DB_L    (OB_DB_H + (unsigned long long)BH)
#define OB_Z_H     (OB_DB_L + (unsigned long long)BH)
#define OB_Z_L     (OB_Z_H + (unsigned long long)BZ)
#define TOTALB     (OB_Z_L + (unsigned long long)BZ)
__device__ __align__(16) __nv_bfloat16 g_bf[TOTALB];

__device__ __forceinline__ float sp_(float x) {
    return fmaxf(x, 0.f) + log1pf(expf(-fabsf(x)));
}
__device__ __forceinline__ float sig_(float x) { return 1.f / (1.f + expf(-x)); }
__device__ __forceinline__ float sig_from_h(float h) { return -expm1f(-h); }

__device__ __forceinline__ void bsplit(float v, __nv_bfloat16& h, __nv_bfloat16& l) {
    __nv_bfloat16 hh = __float2bfloat16(v);
    h = hh;
    l = __float2bfloat16(v - __bfloat162float(hh));
}
__device__ __forceinline__ void split_store2(__nv_bfloat16* Ph, __nv_bfloat16* Pl,
                                             size_t idx, float v0, float v1) {
    __nv_bfloat16 h0, l0, h1, l1;
    bsplit(v0, h0, l0); bsplit(v1, h1, l1);
    *(__nv_bfloat162*)(Ph + idx) = __halves2bfloat162(h0, h1);
    *(__nv_bfloat162*)(Pl + idx) = __halves2bfloat162(l0, l1);
}

// ---------------------------------------------------------------------------
// TN tensor-core GEMM core: C[128,64] += A[128,K]*B[64,K]^T, bf16 hi/lo x3
// ---------------------------------------------------------------------------
#define SA 40
#define OFF_AH 0
#define OFF_AL (128*SA)
#define OFF_BH (2*128*SA)
#define OFF_BL (2*128*SA + 64*SA)
#define STAGE_H (2*128*SA + 2*64*SA)        // 15360 halves = 30720 B
#define SMEM_BYTES (NSTAGE*2*STAGE_H)       // 92160 B

__device__ __forceinline__ void ldsm4(uint32_t* r, uint32_t addr) {
    asm volatile("ldmatrix.sync.aligned.m8n8.x4.shared.b16 {%0,%1,%2,%3}, [%4];\n"
        : "=r"(r[0]), "=r"(r[1]), "=r"(r[2]), "=r"(r[3]) : "r"(addr));
}
__device__ __forceinline__ void mmab(float* c, const uint32_t* a, uint32_t b0, uint32_t b1) {
    asm volatile("mma.sync.aligned.m16n8k16.row.col.f32.bf16.bf16.f32 "
        "{%0,%1,%2,%3},{%4,%5,%6,%7},{%8,%9},{%0,%1,%2,%3};\n"
        : "+f"(c[0]), "+f"(c[1]), "+f"(c[2]), "+f"(c[3])
        : "r"(a[0]), "r"(a[1]), "r"(a[2]), "r"(a[3]), "r"(b0), "r"(b1));
}
__device__ __forceinline__ void cp16(uint32_t dst, const void* src) {
    asm volatile("cp.async.cg.shared.global [%0], [%1], 16;\n" :: "r"(dst), "l"(src));
}
__device__ __forceinline__ void cpcommit() { asm volatile("cp.async.commit_group;\n"); }
template<int N> __device__ __forceinline__ void cpwait() {
    asm volatile("cp.async.wait_group %0;\n" :: "n"(N));
}

__device__ __forceinline__ void ld_stage(uint32_t smst,
    const __nv_bfloat16* __restrict__ Ah, const __nv_bfloat16* __restrict__ Al, int lda,
    const __nv_bfloat16* __restrict__ Bh, const __nv_bfloat16* __restrict__ Bl, int ldb,
    int m0, int n0, int k0, int tid)
{
#pragma unroll
    for (int h = 0; h < 2; h++) {
        int ch = tid + h * 256;
        int row = ch >> 2, kc = ch & 3;
        size_t go = (size_t)(m0 + row) * lda + k0 + kc * 8;
        uint32_t so = smst + 2 * (OFF_AH + row * SA + kc * 8);
        cp16(so, Ah + go);
        cp16(so + 2 * (OFF_AL - OFF_AH), Al + go);
    }
    {
        int row = tid >> 2, kc = tid & 3;
        size_t go = (size_t)(n0 + row) * ldb + k0 + kc * 8;
        uint32_t so = smst + 2 * (OFF_BH + row * SA + kc * 8);
        cp16(so, Bh + go);
        cp16(so + 2 * (OFF_BL - OFF_BH), Bl + go);
    }
}

__device__ __forceinline__ void compute_stage(float acc[2][4][4], uint32_t smst,
                                              int lane, int wm, int wn)
{
#pragma unroll
    for (int kk = 0; kk < 2; kk++) {
        const int k16 = kk * 16;
        uint32_t a0h[4], a1h[4], a0l[4], a1l[4];
        {
            int arow = lane & 15;
            int akoff = k16 + ((lane >> 4) << 3);
            uint32_t ad = smst + 2 * ((wm + arow) * SA + akoff);
            ldsm4(a0h, ad);
            ldsm4(a1h, ad + 2 * 16 * SA);
            ldsm4(a0l, ad + 2 * OFF_AL);
            ldsm4(a1l, ad + 2 * (OFF_AL + 16 * SA));
        }
        uint32_t b0h[4], b1h[4], b0l[4], b1l[4];
        {
            int brow = ((lane >> 4) << 3) + (lane & 7);
            int bkoff = k16 + (((lane >> 3) & 1) << 3);
            uint32_t bd = smst + 2 * (OFF_BH + (wn + brow) * SA + bkoff);
            ldsm4(b0h, bd);
            ldsm4(b1h, bd + 2 * 16 * SA);
            ldsm4(b0l, bd + 2 * (OFF_BL - OFF_BH));
            ldsm4(b1l, bd + 2 * (OFF_BL - OFF_BH) + 2 * 16 * SA);
        }
#pragma unroll
        for (int mi = 0; mi < 2; mi++) {
            const uint32_t* Ahf = mi ? a1h : a0h;
            const uint32_t* Alf = mi ? a1l : a0l;
#pragma unroll
            for (int ni = 0; ni < 4; ni++) {
                const uint32_t* Bhf = (ni < 2) ? b0h : b1h;
                const uint32_t* Blf = (ni < 2) ? b0l : b1l;
                int h2 = (ni & 1) * 2;
                mmab(acc[mi][ni], Ahf, Bhf[h2], Bhf[h2 + 1]);
                mmab(acc[mi][ni], Ahf, Blf[h2], Blf[h2 + 1]);
                mmab(acc[mi][ni], Alf, Bhf[h2], Bhf[h2 + 1]);
            }
        }
    }
}

// Merged two-segment pipeline. One sync/iter; loads issued BEFORE compute.
// Safety: buffer (t+2)%3 was last read by compute(t-1); every warp reaching
// this iteration's __syncthreads has finished compute(t-1).
// Wait counts: at iter t, groups g0..g_{t+1} committed; need g_t done ->
// wait<1> while t+1<kt, wait<0> on the last iteration.
__device__ __forceinline__ void gemm_tn2(float acc[2][4][4], uint32_t smbase,
    const __nv_bfloat16* A1h, const __nv_bfloat16* A1l, int lda1,
    const __nv_bfloat16* B1h, const __nv_bfloat16* B1l, int ldb1, int kt1, int n01,
    const __nv_bfloat16* A2h, const __nv_bfloat16* A2l, int lda2,
    const __nv_bfloat16* B2h, const __nv_bfloat16* B2l, int ldb2, int kt2, int n02,
    int m0, int tid, int lane, int wm, int wn)
{
    const int kt = kt1 + kt2;
    __syncthreads();                // previous users of smem done
    ld_stage(smbase, A1h, A1l, lda1, B1h, B1l, ldb1, m0, n01, 0, tid);
    cpcommit();
    {
        int t = 1;
        if (t < kt) {
            uint32_t st = smbase + 2 * STAGE_H;
            if (t < kt1) ld_stage(st, A1h, A1l, lda1, B1h, B1l, ldb1, m0, n01, t * BKT, tid);
            else         ld_stage(st, A2h, A2l, lda2, B2h, B2l, ldb2, m0, n02, (t - kt1) * BKT, tid);
            cpcommit();
        }
    }
    for (int t = 0; t < kt; t++) {
        if (t + 1 < kt) cpwait<1>(); else cpwait<0>();
        __syncthreads();
        if (t + 2 < kt) {
            int tn = t + 2;
            uint32_t st = smbase + (tn % 3) * 2 * STAGE_H;
            if (tn < kt1) ld_stage(st, A1h, A1l, lda1, B1h, B1l, ldb1, m0, n01, tn * BKT, tid);
            else          ld_stage(st, A2h, A2l, lda2, B2h, B2l, ldb2, m0, n02, (tn - kt1) * BKT, tid);
            cpcommit();
        }
        compute_stage(acc, smbase + (t % 3) * 2 * STAGE_H, lane, wm, wn);
    }
}

// ---------------------------------------------------------------------------
// fp32 SIMT kpre (runs once): c[s] = [x|u] @ W_s[:,256:]^T + bias_s
// ---------------------------------------------------------------------------
__device__ __forceinline__ void mm_compute(float acc[8][4],
    const float As[BK][BM + 4], const float Bs[BK][BN], int tx, int ty)
{
#pragma unroll
    for (int kk = 0; kk < BK; kk++) {
        float4 a0 = *reinterpret_cast<const float4*>(&As[kk][ty * 8]);
        float4 a1 = *reinterpret_cast<const float4*>(&As[kk][ty * 8 + 4]);
        float4 b  = *reinterpret_cast<const float4*>(&Bs[kk][tx * 4]);
        float av[8] = {a0.x, a0.y, a0.z, a0.w, a1.x, a1.y, a1.z, a1.w};
        float bv[4] = {b.x, b.y, b.z, b.w};
#pragma unroll
        for (int i = 0; i < 8; i++)
#pragma unroll
            for (int j = 0; j < 4; j++)
                acc[i][j] = fmaf(av[i], bv[j], acc[i][j]);
    }
}
__device__ __forceinline__ void st_nt(float As[BK][BM + 4], float Bs[BK][BN],
                                      int r, int c, float4 va0, float4 va1, float4 vb)
{
    As[c + 0][r] = va0.x; As[c + 1][r] = va0.y; As[c + 2][r] = va0.z; As[c + 3][r] = va0.w;
    As[c + 0][r + 64] = va1.x; As[c + 1][r + 64] = va1.y; As[c + 2][r + 64] = va1.z; As[c + 3][r + 64] = va1.w;
    Bs[c + 0][r] = vb.x; Bs[c + 1][r] = vb.y; Bs[c + 2][r] = vb.z; Bs[c + 3][r] = vb.w;
}

__global__ void __launch_bounds__(NTHR) kpre(
    const float* __restrict__ x, const float* __restrict__ u,
    const float* __restrict__ W_in, const float* __restrict__ b_in,
    const float* __restrict__ Wxs, const float* __restrict__ bs)
{
    __shared__ float As[2][BK][BM + 4];
    __shared__ float Bs[2][BK][BN];
    const int tid = threadIdx.x, tx = tid & 15, ty = tid >> 4;
    const int m0 = blockIdx.y * BM, n0 = blockIdx.x * BN;
    const int s = blockIdx.z;
    const float* W    = (s == 0) ? W_in : Wxs + (size_t)(s - 1) * HH;
    const float* bias = (s == 0) ? b_in : bs + (size_t)(s - 1) * Hd;
    float* Out = g_buf + O_C + (size_t)s * BH;

    float acc[8][4];
#pragma unroll
    for (int i = 0; i < 8; i++)
#pragma unroll
        for (int j = 0; j < 4; j++) acc[i][j] = 0.f;

    const int r = tid >> 2;
    const int c = (tid & 3) * 4;
    const int kt = 576 / BK;
    const float* Bp = W + (size_t)(n0 + r) * Hd + 256 + c;

    float4 va0, va1, vb;
    va0 = *reinterpret_cast<const float4*>(&x[(size_t)(m0 + r) * 512 + c]);
    va1 = *reinterpret_cast<const float4*>(&x[(size_t)(m0 + r + 64) * 512 + c]);
    vb  = *reinterpret_cast<const float4*>(Bp);
    __syncthreads();
    st_nt(As[0], Bs[0], r, c, va0, va1, vb);
    __syncthreads();

    for (int t = 0; t < kt; t++) {
        int buf = t & 1;
        if (t + 1 < kt) {
            int k = (t + 1) * BK + c;
            if (k < 512) {
                va0 = *reinterpret_cast<const float4*>(&x[(size_t)(m0 + r) * 512 + k]);
                va1 = *reinterpret_cast<const float4*>(&x[(size_t)(m0 + r + 64) * 512 + k]);
            } else {
                va0 = *reinterpret_cast<const float4*>(&u[(size_t)(m0 + r) * 64 + (k - 512)]);
                va1 = *reinterpret_cast<const float4*>(&u[(size_t)(m0 + r + 64) * 64 + (k - 512)]);
            }
            vb = *reinterpret_cast<const float4*>(Bp + (t + 1) * BK);
        }
        mm_compute(acc, As[buf], Bs[buf], tx, ty);
        if (t + 1 < kt) st_nt(As[buf ^ 1], Bs[buf ^ 1], r, c, va0, va1, vb);
        __syncthreads();
    }

    const float4 b4 = *reinterpret_cast<const float4*>(&bias[n0 + tx * 4]);
#pragma unroll
    for (int i = 0; i < 8; i++) {
        int m = m0 + ty * 8 + i;
        float4 o;
        o.x = acc[i][0] + b4.x; o.y = acc[i][1] + b4.y;
        o.z = acc[i][2] + b4.z; o.w = acc[i][3] + b4.w;
        *reinterpret_cast<float4*>(&Out[(size_t)m * Hd + n0 + tx * 4]) = o;
    }
}

// ---------------------------------------------------------------------------
// Prep: weight splits/transposes + state init
// ---------------------------------------------------------------------------
__global__ void kprep(const float* __restrict__ Wzs, const float* __restrict__ wz_out,
                      const float* __restrict__ W_in, const float* __restrict__ Wxs,
                      float* __restrict__ Z)
{
    __nv_bfloat16* bf = g_bf;
    float* SWZO = g_buf + O_SWZO;
    float* Mm = g_buf + O_M;
    float* Vv = g_buf + O_V;
    const int n = 3 * HH;
    for (int i = blockIdx.x * blockDim.x + threadIdx.x; i < n;
         i += gridDim.x * blockDim.x) {
        int l = i / HH, o = i - l * HH;
        int r = o / Hd, c = o - r * Hd;
        float w = sp_(Wzs[i]);
        bsplit(w, bf[OB_SWZF_H + i], bf[OB_SWZF_L + i]);
        size_t ti = (size_t)l * HH + (size_t)c * Hd + r;
        bsplit(w, bf[OB_SWZT_H + ti], bf[OB_SWZT_L + ti]);
        if (c < Zd) {
            float wx = Wxs[i];
            size_t zi = (size_t)l * (Hd * Zd) + (size_t)r * Zd + c;
            bsplit(wx, bf[OB_WXZ_H + zi], bf[OB_WXZ_L + zi]);
            size_t zt = (size_t)l * (Zd * Hd) + (size_t)c * Hd + r;
            bsplit(wx, bf[OB_WXZT_H + zt], bf[OB_WXZT_L + zt]);
            if (l == 0) {
                float wi = W_in[o];
                bsplit(wi, bf[OB_WINZ_H + (size_t)r * Zd + c],
                           bf[OB_WINZ_L + (size_t)r * Zd + c]);
                bsplit(wi, bf[OB_WINZT_H + (size_t)c * Hd + r],
                           bf[OB_WINZT_L + (size_t)c * Hd + r]);
            }
        }
        if (i < Hd) SWZO[i] = sp_(wz_out[i]);
        if (i < BZ) {
            Z[i] = 0.f; Mm[i] = 0.f; Vv[i] = 0.f;
            bf[OB_Z_H + i] = __float2bfloat16(0.f);
            bf[OB_Z_L + i] = __float2bfloat16(0.f);
        }
    }
}

// ---------------------------------------------------------------------------
// Forward: MODE 0 input layer, MODE 1 hidden, MODE 2 hidden+final (emits d3)
// ---------------------------------------------------------------------------
template<int MODE>
__global__ void __launch_bounds__(NTHR, 2) kfwd(
    const __nv_bfloat16* __restrict__ A1h, const __nv_bfloat16* __restrict__ A1l,
    const __nv_bfloat16* __restrict__ B1h, const __nv_bfloat16* __restrict__ B1l,
    const __nv_bfloat16* __restrict__ A2h, const __nv_bfloat16* __restrict__ A2l,
    const __nv_bfloat16* __restrict__ B2h, const __nv_bfloat16* __restrict__ B2l,
    const float* __restrict__ C0,
    __nv_bfloat16* __restrict__ Oh, __nv_bfloat16* __restrict__ Ol)
{
    extern __shared__ __align__(16) char dsm[];
    uint32_t smbase = (uint32_t)__cvta_generic_to_shared(dsm);
    const int tid = threadIdx.x, lane = tid & 31, wid = tid >> 5;
    const int wm = (wid >> 1) * 32, wn = (wid & 1) * 32;
    const int m0 = blockIdx.y * BM, n0 = blockIdx.x * BN;

    float acc[2][4][4];
#pragma unroll
    for (int a = 0; a < 2; a++)
#pragma unroll
        for (int b = 0; b < 4; b++)
#pragma unroll
            for (int d = 0; d < 4; d++) acc[a][b][d] = 0.f;

    if (MODE == 0) {
        gemm_tn2(acc, smbase, A1h, A1l, Zd, B1h, B1l, Zd, Zd / BKT, n0,
                 A1h, A1l, Zd, B1h, B1l, Zd, 0, n0, m0, tid, lane, wm, wn);
    } else {
        gemm_tn2(acc, smbase, A1h, A1l, Hd, B1h, B1l, Hd, Hd / BKT, n0,
                 A2h, A2l, Zd, B2h, B2l, Zd, Zd / BKT, n0, m0, tid, lane, wm, wn);
    }

    const int l4 = lane >> 2, l2 = (lane & 3) * 2;
#pragma unroll
    for (int mi = 0; mi < 2; mi++)
#pragma unroll
    for (int ni = 0; ni < 4; ni++) {
        int mA = m0 + wm + mi * 16 + l4;
        int n  = n0 + wn + ni * 8 + l2;
        size_t iA = (size_t)mA * Hd + n, iB = iA + 8ull * Hd;
        float2 cA = *(const float2*)(C0 + iA);
        float2 cB = *(const float2*)(C0 + iB);
        float v0 = acc[mi][ni][0] + cA.x, v1 = acc[mi][ni][1] + cA.y;
        float v2 = acc[mi][ni][2] + cB.x, v3 = acc[mi][ni][3] + cB.y;
        if (MODE == 2) {
            const float* SWZO = g_buf + O_SWZO;
            float2 s2 = *(const float2*)(SWZO + n);
            v0 = s2.x * sig_(v0); v1 = s2.y * sig_(v1);
            v2 = s2.x * sig_(v2); v3 = s2.y * sig_(v3);
        } else {
            v0 = sp_(v0); v1 = sp_(v1); v2 = sp_(v2); v3 = sp_(v3);
        }
        split_store2(Oh, Ol, iA, v0, v1);
        split_store2(Oh, Ol, iB, v2, v3);
    }
}

// ---------------------------------------------------------------------------
// Backward hidden layer: n<832 d path, n>=832 gradient path
// ---------------------------------------------------------------------------
template<bool FIRSTG>
__global__ void __launch_bounds__(NTHR, 2) kbwd(
    const __nv_bfloat16* __restrict__ Dh, const __nv_bfloat16* __restrict__ Dl,
    const __nv_bfloat16* __restrict__ STh, const __nv_bfloat16* __restrict__ STl,
    const __nv_bfloat16* __restrict__ XTh, const __nv_bfloat16* __restrict__ XTl,
    const __nv_bfloat16* __restrict__ Hph, const __nv_bfloat16* __restrict__ Hpl,
    __nv_bfloat16* __restrict__ Oh, __nv_bfloat16* __restrict__ Ol,
    const float* __restrict__ wx_out)
{
    extern __shared__ __align__(16) char dsm[];
    uint32_t smbase = (uint32_t)__cvta_generic_to_shared(dsm);
    const int tid = threadIdx.x, lane = tid & 31, wid = tid >> 5;
    const int wm = (wid >> 1) * 32, wn = (wid & 1) * 32;
    const int m0 = blockIdx.y * BM, n0 = blockIdx.x * BN;
    const bool gpath = (n0 >= Hd);
    const int nb = gpath ? (n0 - Hd) : n0;

    float acc[2][4][4];
#pragma unroll
    for (int a = 0; a < 2; a++)
#pragma unroll
        for (int b = 0; b < 4; b++)
#pragma unroll
            for (int d = 0; d < 4; d++) acc[a][b][d] = 0.f;

    gemm_tn2(acc, smbase, Dh, Dl, Hd,
             gpath ? XTh : STh, gpath ? XTl : STl, Hd, Hd / BKT, nb,
             Dh, Dl, Hd, STh, STl, Hd, 0, nb, m0, tid, lane, wm, wn);

    const int l4 = lane >> 2, l2 = (lane & 3) * 2;
    if (!gpath) {
#pragma unroll
        for (int mi = 0; mi < 2; mi++)
#pragma unroll
        for (int ni = 0; ni < 4; ni++) {
            int mA = m0 + wm + mi * 16 + l4;
            int n  = n0 + wn + ni * 8 + l2;
            size_t iA = (size_t)mA * Hd + n, iB = iA + 8ull * Hd;
            __nv_bfloat162 hhA = *(const __nv_bfloat162*)(Hph + iA);
            __nv_bfloat162 hlA = *(const __nv_bfloat162*)(Hpl + iA);
            __nv_bfloat162 hhB = *(const __nv_bfloat162*)(Hph + iB);
            __nv_bfloat162 hlB = *(const __nv_bfloat162*)(Hpl + iB);
            float d0 = acc[mi][ni][0] * sig_from_h(__bfloat162float(hhA.x) + __bfloat162float(hlA.x));
            float d1 = acc[mi][ni][1] * sig_from_h(__bfloat162float(hhA.y) + __bfloat162float(hlA.y));
            float d2 = acc[mi][ni][2] * sig_from_h(__bfloat162float(hhB.x) + __bfloat162float(hlB.x));
            float d3 = acc[mi][ni][3] * sig_from_h(__bfloat162float(hhB.y) + __bfloat162float(hlB.y));
            split_store2(Oh, Ol, iA, d0, d1);
            split_store2(Oh, Ol, iB, d2, d3);
        }
    } else {
        float* G = g_buf + O_G;
#pragma unroll
        for (int mi = 0; mi < 2; mi++)
#pragma unroll
        for (int ni = 0; ni < 4; ni++) {
            int mA = m0 + wm + mi * 16 + l4;
            int np = nb + wn + ni * 8 + l2;
            size_t gA = (size_t)mA * Zd + np, gB = gA + 8ull * Zd;
            float2 bA, bB;
            if (FIRSTG) {
                float2 w2 = *(const float2*)(wx_out + np);
                bA = w2; bB = w2;
            } else {
                bA = *(const float2*)(G + gA);
                bB = *(const float2*)(G + gB);
            }
            float2 oA, oB;
            oA.x = bA.x + acc[mi][ni][0]; oA.y = bA.y + acc[mi][ni][1];
            oB.x = bB.x + acc[mi][ni][2]; oB.y = bB.y + acc[mi][ni][3];
            *(float2*)(G + gA) = oA;
            *(float2*)(G + gB) = oB;
        }
    }
}

// ---------------------------------------------------------------------------
// Final backward + Adam
// ---------------------------------------------------------------------------
__global__ void __launch_bounds__(NTHR, 2) kbwdin(
    const __nv_bfloat16* __restrict__ Dh, const __nv_bfloat16* __restrict__ Dl,
    const __nv_bfloat16* __restrict__ WTh, const __nv_bfloat16* __restrict__ WTl,
    float* __restrict__ Z, __nv_bfloat16* __restrict__ Zh, __nv_bfloat16* __restrict__ Zl,
    float bc1, float bc2)
{
    extern __shared__ __align__(16) char dsm[];
    uint32_t smbase = (uint32_t)__cvta_generic_to_shared(dsm);
    const int tid = threadIdx.x, lane = tid & 31, wid = tid >> 5;
    const int wm = (wid >> 1) * 32, wn = (wid & 1) * 32;
    const int m0 = blockIdx.y * BM, n0 = blockIdx.x * BN;

    float acc[2][4][4];
#pragma unroll
    for (int a = 0; a < 2; a++)
#pragma unroll
        for (int b = 0; b < 4; b++)
#pragma unroll
            for (int d = 0; d < 4; d++) acc[a][b][d] = 0.f;

    gemm_tn2(acc, smbase, Dh, Dl, Hd, WTh, WTl, Hd, Hd / BKT, n0,
             Dh, Dl, Hd, WTh, WTl, Hd, 0, n0, m0, tid, lane, wm, wn);

    const float* G = g_buf + O_G;
    float* Mm = g_buf + O_M;
    float* Vv = g_buf + O_V;
    const int l4 = lane >> 2, l2 = (lane & 3) * 2;
#pragma unroll
    for (int mi = 0; mi < 2; mi++)
#pragma unroll
    for (int ni = 0; ni < 4; ni++) {
        int mA = m0 + wm + mi * 16 + l4;
        int np = n0 + wn + ni * 8 + l2;
        size_t idx[2];
        idx[0] = (size_t)mA * Zd + np;
        idx[1] = idx[0] + 8ull * Zd;
#pragma unroll
        for (int hh = 0; hh < 2; hh++) {
            size_t id = idx[hh];
            float g0 = G[id]     + acc[mi][ni][hh * 2 + 0];
            float g1 = G[id + 1] + acc[mi][ni][hh * 2 + 1];
            float2 m2 = *(const float2*)(Mm + id);
            float2 v2 = *(const float2*)(Vv + id);
            float nm0 = 0.9f * m2.x + 0.1f * g0;
            float nm1 = 0.9f * m2.y + 0.1f * g1;
            float nv0 = 0.999f * v2.x + 0.001f * g0 * g0;
            float nv1 = 0.999f * v2.y + 0.001f * g1 * g1;
            *(float2*)(Mm + id) = make_float2(nm0, nm1);
            *(float2*)(Vv + id) = make_float2(nv0, nv1);
            float2 z2 = *(const float2*)(Z + id);
            z2.x -= 0.01f * (nm0 * bc1) / (sqrtf(nv0 * bc2) + 1e-8f);
            z2.y -= 0.01f * (nm1 * bc1) / (sqrtf(nv1 * bc2) + 1e-8f);
            *(float2*)(Z + id) = z2;
            split_store2(Zh, Zl, id, z2.x, z2.y);
        }
    }
}

// ---------------------------------------------------------------------------
// Host driver
// ---------------------------------------------------------------------------
extern "C" void kernel_launch(void* const* d_in, const int* in_sizes, int n_in,
                              void* d_out, int out_size)
{
    (void)in_sizes; (void)n_in; (void)out_size;
    const float* x      = (const float*)d_in[0];
    const float* u      = (const float*)d_in[1];
    const float* W_in   = (const float*)d_in[2];
    const float* b_in   = (const float*)d_in[3];
    const float* Wzs    = (const float*)d_in[4];
    const float* Wxs    = (const float*)d_in[5];
    const float* bs     = (const float*)d_in[6];
    const float* wz_out = (const float*)d_in[7];
    const float* wx_out = (const float*)d_in[8];
    float* z = (float*)d_out;

    float* buf = nullptr;
    { void* p = nullptr; cudaGetSymbolAddress(&p, g_buf); buf = (float*)p; }
    __nv_bfloat16* bb = nullptr;
    { void* p = nullptr; cudaGetSymbolAddress(&p, g_bf); bb = (__nv_bfloat16*)p; }

    float* C = buf + O_C;

    static bool attr_done = false;
    if (!attr_done) {
        cudaFuncSetAttribute(kfwd<0>, cudaFuncAttributeMaxDynamicSharedMemorySize, SMEM_BYTES);
        cudaFuncSetAttribute(kfwd<1>, cudaFuncAttributeMaxDynamicSharedMemorySize, SMEM_BYTES);
        cudaFuncSetAttribute(kfwd<2>, cudaFuncAttributeMaxDynamicSharedMemorySize, SMEM_BYTES);
        cudaFuncSetAttribute(kbwd<true>,  cudaFuncAttributeMaxDynamicSharedMemorySize, SMEM_BYTES);
        cudaFuncSetAttribute(kbwd<false>, cudaFuncAttributeMaxDynamicSharedMemorySize, SMEM_BYTES);
        cudaFuncSetAttribute(kbwdin, cudaFuncAttributeMaxDynamicSharedMemorySize, SMEM_BYTES);
        attr_done = true;
    }

    dim3 blk(NTHR);
    kprep<<<2048, 512>>>(Wzs, wz_out, W_in, Wxs, z);
    kpre<<<dim3(Hd / BN, Bsz / BM, 4), blk>>>(x, u, W_in, b_in, Wxs, bs);

    const dim3 gF(Hd / BN, Bsz / BM);            // 13 x 32
    const dim3 gB((Hd + Zd) / BN, Bsz / BM);     // 17 x 32
    const dim3 gI(Zd / BN, Bsz / BM);            // 4 x 32

    __nv_bfloat16 *Zh = bb + OB_Z_H, *Zl = bb + OB_Z_L;
    __nv_bfloat16 *DAh = bb + OB_DA_H, *DAl = bb + OB_DA_L;
    __nv_bfloat16 *DBh = bb + OB_DB_H, *DBl = bb + OB_DB_L;

    for (int t = 0; t < NSTEPS; t++) {
        kfwd<0><<<gF, blk, SMEM_BYTES>>>(
            Zh, Zl, bb + OB_WINZ_H, bb + OB_WINZ_L,
            (const __nv_bfloat16*)nullptr, (const __nv_bfloat16*)nullptr,
            (const __nv_bfloat16*)nullptr, (const __nv_bfloat16*)nullptr,
            C, bb + OB_H_H, bb + OB_H_L);
        for (int l = 0; l < 3; l++) {
            __nv_bfloat16* Ah = bb + OB_H_H + (size_t)l * BH;
            __nv_bfloat16* Al = bb + OB_H_L + (size_t)l * BH;
            __nv_bfloat16* Oh = (l < 2) ? bb + OB_H_H + (size_t)(l + 1) * BH : DAh;
            __nv_bfloat16* Ol = (l < 2) ? bb + OB_H_L + (size_t)(l + 1) * BH : DAl;
            if (l < 2)
                kfwd<1><<<gF, blk, SMEM_BYTES>>>(
                    Ah, Al, bb + OB_SWZF_H + (size_t)l * HH, bb + OB_SWZF_L + (size_t)l * HH,
                    Zh, Zl, bb + OB_WXZ_H + (size_t)l * (Hd * Zd), bb + OB_WXZ_L + (size_t)l * (Hd * Zd),
                    C + (size_t)(l + 1) * BH, Oh, Ol);
            else
                kfwd<2><<<gF, blk, SMEM_BYTES>>>(
                    Ah, Al, bb + OB_SWZF_H + (size_t)l * HH, bb + OB_SWZF_L + (size_t)l * HH,
                    Zh, Zl, bb + OB_WXZ_H + (size_t)l * (Hd * Zd), bb + OB_WXZ_L + (size_t)l * (Hd * Zd),
                    C + (size_t)(l + 1) * BH, Oh, Ol);
        }
        kbwd<true><<<gB, blk, SMEM_BYTES>>>(
            DAh, DAl,
            bb + OB_SWZT_H + 2ull * HH, bb + OB_SWZT_L + 2ull * HH,
            bb + OB_WXZT_H + 2ull * (Zd * Hd), bb + OB_WXZT_L + 2ull * (Zd * Hd),
            bb + OB_H_H + 2ull * BH, bb + OB_H_L + 2ull * BH,
            DBh, DBl, wx_out);
        kbwd<false><<<gB, blk, SMEM_BYTES>>>(
            DBh, DBl,
            bb + OB_SWZT_H + 1ull * HH, bb + OB_SWZT_L + 1ull * HH,
            bb + OB_WXZT_H + 1ull * (Zd * Hd), bb + OB_WXZT_L + 1ull * (Zd * Hd),
            bb + OB_H_H + 1ull * BH, bb + OB_H_L + 1ull * BH,
            DAh, DAl, wx_out);
        kbwd<false><<<gB, blk, SMEM_BYTES>>>(
            DAh, DAl,
            bb + OB_SWZT_H, bb + OB_SWZT_L,
            bb + OB_WXZT_H, bb + OB_WXZT_L,
            bb + OB_H_H, bb + OB_H_L,
            DBh, DBl, wx_out);
        double p1 = 1.0, p2 = 1.0;
        for (int q = 0; q <= t; q++) { p1 *= 0.9; p2 *= 0.999; }
        float bc1 = (float)(1.0 / (1.0 - p1));
        float bc2 = (float)(1.0 / (1.0 - p2));
        kbwdin<<<gI, blk, SMEM_BYTES>>>(
            DBh, DBl, bb + OB_WINZT_H, bb + OB_WINZT_L,
            z, Zh, Zl, bc1, bc2);
    }
}

// round 8
// speedup vs baseline: 1.0126x; 1.0126x over previous
#include <cuda_runtime.h>
#include <cuda_bf16.h>
#include <math.h>
#include <stdint.h>

// ---------------------------------------------------------------------------
// KoopmanPhiICNN encode, R8: bf16x3 mma.sync GEMMs. R6 pipeline (3-stage
// cp.async, loads after compute, two static gemm_tn calls) + 512-thread CTAs
// (16 warps, warp tile 16x32) for 2x warp-level parallelism.
// ---------------------------------------------------------------------------

#define Bsz 4096
#define Hd  832
#define Zd  256
#define BH  (Bsz*Hd)
#define HH  (Hd*Hd)
#define BZ  (Bsz*Zd)
#define NSTEPS 64

#define BM 128
#define BN 64
#define BKT 32
#define BK 16
#define NTHR 256      // kpre only
#define GTHR 512      // GEMM kernels
#define NSTAGE 3

// ---- fp32 scratch ----
#define O_SWZO 0ull
#define O_C    (O_SWZO + 1024ull)
#define O_G    (O_C + 4ull*BH)
#define O_M    (O_G + (unsigned long long)BZ)
#define O_V    (O_M + (unsigned long long)BZ)
#define TOTALF (O_V + (unsigned long long)BZ)
__device__ __align__(16) float g_buf[TOTALF];

// ---- bf16 scratch (hi/lo pairs) ----
#define SZ_WINZ  (832ull*256ull)
#define SZ_WXZ   (3ull*832ull*256ull)
#define SZ_SWZ   (3ull*(unsigned long long)HH)
#define OB_WINZ_H  0ull
#define OB_WINZ_L  (OB_WINZ_H + SZ_WINZ)
#define OB_WXZ_H   (OB_WINZ_L + SZ_WINZ)
#define OB_WXZ_L   (OB_WXZ_H + SZ_WXZ)
#define OB_SWZF_H  (OB_WXZ_L + SZ_WXZ)
#define OB_SWZF_L  (OB_SWZF_H + SZ_SWZ)
#define OB_SWZT_H  (OB_SWZF_L + SZ_SWZ)
#define OB_SWZT_L  (OB_SWZT_H + SZ_SWZ)
#define OB_WXZT_H  (OB_SWZT_L + SZ_SWZ)
#define OB_WXZT_L  (OB_WXZT_H + SZ_WXZ)
#define OB_WINZT_H (OB_WXZT_L + SZ_WXZ)
#define OB_WINZT_L (OB_WINZT_H + SZ_WINZ)
#define OB_H_H     (OB_WINZT_L + SZ_WINZ)
#define OB_H_L     (OB_H_H + 3ull*BH)
#define OB_DA_H    (OB_H_L + 3ull*BH)
#define OB_DA_L    (OB_DA_H + (unsigned long long)BH)
#define OB_DB_H    (OB_DA_L + (unsigned long long)BH)
#define OB_DB_L    (OB_DB_H + (unsigned long long)BH)
#define OB_Z_H     (OB_DB_L + (unsigned long long)BH)
#define OB_Z_L     (OB_Z_H + (unsigned long long)BZ)
#define TOTALB     (OB_Z_L + (unsigned long long)BZ)
__device__ __align__(16) __nv_bfloat16 g_bf[TOTALB];

__device__ __forceinline__ float sp_(float x) {
    return fmaxf(x, 0.f) + log1pf(expf(-fabsf(x)));
}
__device__ __forceinline__ float sig_(float x) { return 1.f / (1.f + expf(-x)); }
__device__ __forceinline__ float sig_from_h(float h) { return -expm1f(-h); }

__device__ __forceinline__ void bsplit(float v, __nv_bfloat16& h, __nv_bfloat16& l) {
    __nv_bfloat16 hh = __float2bfloat16(v);
    h = hh;
    l = __float2bfloat16(v - __bfloat162float(hh));
}
__device__ __forceinline__ void split_store2(__nv_bfloat16* Ph, __nv_bfloat16* Pl,
                                             size_t idx, float v0, float v1) {
    __nv_bfloat16 h0, l0, h1, l1;
    bsplit(v0, h0, l0); bsplit(v1, h1, l1);
    *(__nv_bfloat162*)(Ph + idx) = __halves2bfloat162(h0, h1);
    *(__nv_bfloat162*)(Pl + idx) = __halves2bfloat162(l0, l1);
}

// ---------------------------------------------------------------------------
// TN tensor-core GEMM core: C[128,64] += A[128,K]*B[64,K]^T, bf16 hi/lo x3
// 16 warps, warp tile 16x32 (8 M-tiles x 2 N-tiles).
// ---------------------------------------------------------------------------
#define SA 40
#define OFF_AH 0
#define OFF_AL (128*SA)
#define OFF_BH (2*128*SA)
#define OFF_BL (2*128*SA + 64*SA)
#define STAGE_H (2*128*SA + 2*64*SA)        // 15360 halves = 30720 B
#define SMEM_BYTES (NSTAGE*2*STAGE_H)       // 92160 B

__device__ __forceinline__ void ldsm4(uint32_t* r, uint32_t addr) {
    asm volatile("ldmatrix.sync.aligned.m8n8.x4.shared.b16 {%0,%1,%2,%3}, [%4];\n"
        : "=r"(r[0]), "=r"(r[1]), "=r"(r[2]), "=r"(r[3]) : "r"(addr));
}
__device__ __forceinline__ void mmab(float* c, const uint32_t* a, uint32_t b0, uint32_t b1) {
    asm volatile("mma.sync.aligned.m16n8k16.row.col.f32.bf16.bf16.f32 "
        "{%0,%1,%2,%3},{%4,%5,%6,%7},{%8,%9},{%0,%1,%2,%3};\n"
        : "+f"(c[0]), "+f"(c[1]), "+f"(c[2]), "+f"(c[3])
        : "r"(a[0]), "r"(a[1]), "r"(a[2]), "r"(a[3]), "r"(b0), "r"(b1));
}
__device__ __forceinline__ void cp16(uint32_t dst, const void* src) {
    asm volatile("cp.async.cg.shared.global [%0], [%1], 16;\n" :: "r"(dst), "l"(src));
}
__device__ __forceinline__ void cpcommit() { asm volatile("cp.async.commit_group;\n"); }
template<int N> __device__ __forceinline__ void cpwait() {
    asm volatile("cp.async.wait_group %0;\n" :: "n"(N));
}

// 512 threads: A (128 rows x 4 chunks, hi+lo) 1 chunk-pair/thread;
// B (64 rows x 4 chunks, hi+lo) on threads < 256.
__device__ __forceinline__ void ld_stage(uint32_t smst,
    const __nv_bfloat16* __restrict__ Ah, const __nv_bfloat16* __restrict__ Al, int lda,
    const __nv_bfloat16* __restrict__ Bh, const __nv_bfloat16* __restrict__ Bl, int ldb,
    int m0, int n0, int k0, int tid)
{
    {
        int row = tid >> 2, kc = tid & 3;
        size_t go = (size_t)(m0 + row) * lda + k0 + kc * 8;
        uint32_t so = smst + 2 * (OFF_AH + row * SA + kc * 8);
        cp16(so, Ah + go);
        cp16(so + 2 * (OFF_AL - OFF_AH), Al + go);
    }
    if (tid < 256) {
        int row = tid >> 2, kc = tid & 3;
        size_t go = (size_t)(n0 + row) * ldb + k0 + kc * 8;
        uint32_t so = smst + 2 * (OFF_BH + row * SA + kc * 8);
        cp16(so, Bh + go);
        cp16(so + 2 * (OFF_BL - OFF_BH), Bl + go);
    }
}

// Warp tile 16x32: acc[4][4] (ni = 4 n8 tiles).
__device__ __forceinline__ void compute_stage(float acc[4][4], uint32_t smst,
                                              int lane, int wm, int wn)
{
#pragma unroll
    for (int kk = 0; kk < 2; kk++) {
        const int k16 = kk * 16;
        uint32_t ah[4], al[4];
        {
            int arow = lane & 15;
            int akoff = k16 + ((lane >> 4) << 3);
            uint32_t ad = smst + 2 * ((wm + arow) * SA + akoff);
            ldsm4(ah, ad);
            ldsm4(al, ad + 2 * OFF_AL);
        }
        uint32_t b0h[4], b1h[4], b0l[4], b1l[4];
        {
            int brow = ((lane >> 4) << 3) + (lane & 7);
            int bkoff = k16 + (((lane >> 3) & 1) << 3);
            uint32_t bd = smst + 2 * (OFF_BH + (wn + brow) * SA + bkoff);
            ldsm4(b0h, bd);
            ldsm4(b1h, bd + 2 * 16 * SA);
            ldsm4(b0l, bd + 2 * (OFF_BL - OFF_BH));
            ldsm4(b1l, bd + 2 * (OFF_BL - OFF_BH) + 2 * 16 * SA);
        }
#pragma unroll
        for (int ni = 0; ni < 4; ni++) {
            const uint32_t* Bhf = (ni < 2) ? b0h : b1h;
            const uint32_t* Blf = (ni < 2) ? b0l : b1l;
            int h2 = (ni & 1) * 2;
            mmab(acc[ni], ah, Bhf[h2], Bhf[h2 + 1]);
            mmab(acc[ni], ah, Blf[h2], Blf[h2 + 1]);
            mmab(acc[ni], al, Bhf[h2], Bhf[h2 + 1]);
        }
    }
}

// R6-proven 3-stage pipeline: one barrier per stage, loads after compute.
__device__ __forceinline__ void gemm_tn(float acc[4][4], uint32_t smbase,
    const __nv_bfloat16* Ah, const __nv_bfloat16* Al, int lda,
    const __nv_bfloat16* Bh, const __nv_bfloat16* Bl, int ldb,
    int kt, int m0, int n0, int tid, int lane, int wm, int wn)
{
    __syncthreads();   // previous users of smem done
    ld_stage(smbase, Ah, Al, lda, Bh, Bl, ldb, m0, n0, 0, tid);
    cpcommit();
    if (kt > 1) ld_stage(smbase + 2 * STAGE_H, Ah, Al, lda, Bh, Bl, ldb, m0, n0, BKT, tid);
    cpcommit();

    for (int t = 0; t < kt; t++) {
        cpwait<1>();
        __syncthreads();
        compute_stage(acc, smbase + (t % 3) * 2 * STAGE_H, lane, wm, wn);
        if (t + 2 < kt)
            ld_stage(smbase + ((t + 2) % 3) * 2 * STAGE_H,
                     Ah, Al, lda, Bh, Bl, ldb, m0, n0, (t + 2) * BKT, tid);
        cpcommit();
    }
    cpwait<0>();
}

// ---------------------------------------------------------------------------
// fp32 SIMT kpre (runs once): c[s] = [x|u] @ W_s[:,256:]^T + bias_s
// ---------------------------------------------------------------------------
__device__ __forceinline__ void mm_compute(float acc[8][4],
    const float As[BK][BM + 4], const float Bs[BK][BN], int tx, int ty)
{
#pragma unroll
    for (int kk = 0; kk < BK; kk++) {
        float4 a0 = *reinterpret_cast<const float4*>(&As[kk][ty * 8]);
        float4 a1 = *reinterpret_cast<const float4*>(&As[kk][ty * 8 + 4]);
        float4 b  = *reinterpret_cast<const float4*>(&Bs[kk][tx * 4]);
        float av[8] = {a0.x, a0.y, a0.z, a0.w, a1.x, a1.y, a1.z, a1.w};
        float bv[4] = {b.x, b.y, b.z, b.w};
#pragma unroll
        for (int i = 0; i < 8; i++)
#pragma unroll
            for (int j = 0; j < 4; j++)
                acc[i][j] = fmaf(av[i], bv[j], acc[i][j]);
    }
}
__device__ __forceinline__ void st_nt(float As[BK][BM + 4], float Bs[BK][BN],
                                      int r, int c, float4 va0, float4 va1, float4 vb)
{
    As[c + 0][r] = va0.x; As[c + 1][r] = va0.y; As[c + 2][r] = va0.z; As[c + 3][r] = va0.w;
    As[c + 0][r + 64] = va1.x; As[c + 1][r + 64] = va1.y; As[c + 2][r + 64] = va1.z; As[c + 3][r + 64] = va1.w;
    Bs[c + 0][r] = vb.x; Bs[c + 1][r] = vb.y; Bs[c + 2][r] = vb.z; Bs[c + 3][r] = vb.w;
}

__global__ void __launch_bounds__(NTHR) kpre(
    const float* __restrict__ x, const float* __restrict__ u,
    const float* __restrict__ W_in, const float* __restrict__ b_in,
    const float* __restrict__ Wxs, const float* __restrict__ bs)
{
    __shared__ float As[2][BK][BM + 4];
    __shared__ float Bs[2][BK][BN];
    const int tid = threadIdx.x, tx = tid & 15, ty = tid >> 4;
    const int m0 = blockIdx.y * BM, n0 = blockIdx.x * BN;
    const int s = blockIdx.z;
    const float* W    = (s == 0) ? W_in : Wxs + (size_t)(s - 1) * HH;
    const float* bias = (s == 0) ? b_in : bs + (size_t)(s - 1) * Hd;
    float* Out = g_buf + O_C + (size_t)s * BH;

    float acc[8][4];
#pragma unroll
    for (int i = 0; i < 8; i++)
#pragma unroll
        for (int j = 0; j < 4; j++) acc[i][j] = 0.f;

    const int r = tid >> 2;
    const int c = (tid & 3) * 4;
    const int kt = 576 / BK;
    const float* Bp = W + (size_t)(n0 + r) * Hd + 256 + c;

    float4 va0, va1, vb;
    va0 = *reinterpret_cast<const float4*>(&x[(size_t)(m0 + r) * 512 + c]);
    va1 = *reinterpret_cast<const float4*>(&x[(size_t)(m0 + r + 64) * 512 + c]);
    vb  = *reinterpret_cast<const float4*>(Bp);
    __syncthreads();
    st_nt(As[0], Bs[0], r, c, va0, va1, vb);
    __syncthreads();

    for (int t = 0; t < kt; t++) {
        int buf = t & 1;
        if (t + 1 < kt) {
            int k = (t + 1) * BK + c;
            if (k < 512) {
                va0 = *reinterpret_cast<const float4*>(&x[(size_t)(m0 + r) * 512 + k]);
                va1 = *reinterpret_cast<const float4*>(&x[(size_t)(m0 + r + 64) * 512 + k]);
            } else {
                va0 = *reinterpret_cast<const float4*>(&u[(size_t)(m0 + r) * 64 + (k - 512)]);
                va1 = *reinterpret_cast<const float4*>(&u[(size_t)(m0 + r + 64) * 64 + (k - 512)]);
            }
            vb = *reinterpret_cast<const float4*>(Bp + (t + 1) * BK);
        }
        mm_compute(acc, As[buf], Bs[buf], tx, ty);
        if (t + 1 < kt) st_nt(As[buf ^ 1], Bs[buf ^ 1], r, c, va0, va1, vb);
        __syncthreads();
    }

    const float4 b4 = *reinterpret_cast<const float4*>(&bias[n0 + tx * 4]);
#pragma unroll
    for (int i = 0; i < 8; i++) {
        int m = m0 + ty * 8 + i;
        float4 o;
        o.x = acc[i][0] + b4.x; o.y = acc[i][1] + b4.y;
        o.z = acc[i][2] + b4.z; o.w = acc[i][3] + b4.w;
        *reinterpret_cast<float4*>(&Out[(size_t)m * Hd + n0 + tx * 4]) = o;
    }
}

// ---------------------------------------------------------------------------
// Prep: weight splits/transposes + state init
// ---------------------------------------------------------------------------
__global__ void kprep(const float* __restrict__ Wzs, const float* __restrict__ wz_out,
                      const float* __restrict__ W_in, const float* __restrict__ Wxs,
                      float* __restrict__ Z)
{
    __nv_bfloat16* bf = g_bf;
    float* SWZO = g_buf + O_SWZO;
    float* Mm = g_buf + O_M;
    float* Vv = g_buf + O_V;
    const int n = 3 * HH;
    for (int i = blockIdx.x * blockDim.x + threadIdx.x; i < n;
         i += gridDim.x * blockDim.x) {
        int l = i / HH, o = i - l * HH;
        int r = o / Hd, c = o - r * Hd;
        float w = sp_(Wzs[i]);
        bsplit(w, bf[OB_SWZF_H + i], bf[OB_SWZF_L + i]);
        size_t ti = (size_t)l * HH + (size_t)c * Hd + r;
        bsplit(w, bf[OB_SWZT_H + ti], bf[OB_SWZT_L + ti]);
        if (c < Zd) {
            float wx = Wxs[i];
            size_t zi = (size_t)l * (Hd * Zd) + (size_t)r * Zd + c;
            bsplit(wx, bf[OB_WXZ_H + zi], bf[OB_WXZ_L + zi]);
            size_t zt = (size_t)l * (Zd * Hd) + (size_t)c * Hd + r;
            bsplit(wx, bf[OB_WXZT_H + zt], bf[OB_WXZT_L + zt]);
            if (l == 0) {
                float wi = W_in[o];
                bsplit(wi, bf[OB_WINZ_H + (size_t)r * Zd + c],
                           bf[OB_WINZ_L + (size_t)r * Zd + c]);
                bsplit(wi, bf[OB_WINZT_H + (size_t)c * Hd + r],
                           bf[OB_WINZT_L + (size_t)c * Hd + r]);
            }
        }
        if (i < Hd) SWZO[i] = sp_(wz_out[i]);
        if (i < BZ) {
            Z[i] = 0.f; Mm[i] = 0.f; Vv[i] = 0.f;
            bf[OB_Z_H + i] = __float2bfloat16(0.f);
            bf[OB_Z_L + i] = __float2bfloat16(0.f);
        }
    }
}

// ---------------------------------------------------------------------------
// Forward: MODE 0 input layer, MODE 1 hidden, MODE 2 hidden+final (emits d3)
// ---------------------------------------------------------------------------
template<int MODE>
__global__ void __launch_bounds__(GTHR, 2) kfwd(
    const __nv_bfloat16* __restrict__ A1h, const __nv_bfloat16* __restrict__ A1l,
    const __nv_bfloat16* __restrict__ B1h, const __nv_bfloat16* __restrict__ B1l,
    const __nv_bfloat16* __restrict__ A2h, const __nv_bfloat16* __restrict__ A2l,
    const __nv_bfloat16* __restrict__ B2h, const __nv_bfloat16* __restrict__ B2l,
    const float* __restrict__ C0,
    __nv_bfloat16* __restrict__ Oh, __nv_bfloat16* __restrict__ Ol)
{
    extern __shared__ __align__(16) char dsm[];
    uint32_t smbase = (uint32_t)__cvta_generic_to_shared(dsm);
    const int tid = threadIdx.x, lane = tid & 31, wid = tid >> 5;
    const int wm = (wid >> 1) * 16, wn = (wid & 1) * 32;
    const int m0 = blockIdx.y * BM, n0 = blockIdx.x * BN;

    float acc[4][4];
#pragma unroll
    for (int b = 0; b < 4; b++)
#pragma unroll
        for (int d = 0; d < 4; d++) acc[b][d] = 0.f;

    if (MODE == 0) {
        gemm_tn(acc, smbase, A1h, A1l, Zd, B1h, B1l, Zd, Zd / BKT, m0, n0, tid, lane, wm, wn);
    } else {
        gemm_tn(acc, smbase, A1h, A1l, Hd, B1h, B1l, Hd, Hd / BKT, m0, n0, tid, lane, wm, wn);
        gemm_tn(acc, smbase, A2h, A2l, Zd, B2h, B2l, Zd, Zd / BKT, m0, n0, tid, lane, wm, wn);
    }

    const int l4 = lane >> 2, l2 = (lane & 3) * 2;
#pragma unroll
    for (int ni = 0; ni < 4; ni++) {
        int mA = m0 + wm + l4;
        int n  = n0 + wn + ni * 8 + l2;
        size_t iA = (size_t)mA * Hd + n, iB = iA + 8ull * Hd;
        float2 cA = *(const float2*)(C0 + iA);
        float2 cB = *(const float2*)(C0 + iB);
        float v0 = acc[ni][0] + cA.x, v1 = acc[ni][1] + cA.y;
        float v2 = acc[ni][2] + cB.x, v3 = acc[ni][3] + cB.y;
        if (MODE == 2) {
            const float* SWZO = g_buf + O_SWZO;
            float2 s2 = *(const float2*)(SWZO + n);
            v0 = s2.x * sig_(v0); v1 = s2.y * sig_(v1);
            v2 = s2.x * sig_(v2); v3 = s2.y * sig_(v3);
        } else {
            v0 = sp_(v0); v1 = sp_(v1); v2 = sp_(v2); v3 = sp_(v3);
        }
        split_store2(Oh, Ol, iA, v0, v1);
        split_store2(Oh, Ol, iB, v2, v3);
    }
}

// ---------------------------------------------------------------------------
// Backward hidden layer: n<832 d path, n>=832 gradient path
// ---------------------------------------------------------------------------
template<bool FIRSTG>
__global__ void __launch_bounds__(GTHR, 2) kbwd(
    const __nv_bfloat16* __restrict__ Dh, const __nv_bfloat16* __restrict__ Dl,
    const __nv_bfloat16* __restrict__ STh, const __nv_bfloat16* __restrict__ STl,
    const __nv_bfloat16* __restrict__ XTh, const __nv_bfloat16* __restrict__ XTl,
    const __nv_bfloat16* __restrict__ Hph, const __nv_bfloat16* __restrict__ Hpl,
    __nv_bfloat16* __restrict__ Oh, __nv_bfloat16* __restrict__ Ol,
    const float* __restrict__ wx_out)
{
    extern __shared__ __align__(16) char dsm[];
    uint32_t smbase = (uint32_t)__cvta_generic_to_shared(dsm);
    const int tid = threadIdx.x, lane = tid & 31, wid = tid >> 5;
    const int wm = (wid >> 1) * 16, wn = (wid & 1) * 32;
    const int m0 = blockIdx.y * BM, n0 = blockIdx.x * BN;
    const bool gpath = (n0 >= Hd);
    const int nb = gpath ? (n0 - Hd) : n0;

    float acc[4][4];
#pragma unroll
    for (int b = 0; b < 4; b++)
#pragma unroll
        for (int d = 0; d < 4; d++) acc[b][d] = 0.f;

    gemm_tn(acc, smbase, Dh, Dl, Hd,
            gpath ? XTh : STh, gpath ? XTl : STl, Hd, Hd / BKT,
            m0, nb, tid, lane, wm, wn);

    const int l4 = lane >> 2, l2 = (lane & 3) * 2;
    if (!gpath) {
#pragma unroll
        for (int ni = 0; ni < 4; ni++) {
            int mA = m0 + wm + l4;
            int n  = n0 + wn + ni * 8 + l2;
            size_t iA = (size_t)mA * Hd + n, iB = iA + 8ull * Hd;
            __nv_bfloat162 hhA = *(const __nv_bfloat162*)(Hph + iA);
            __nv_bfloat162 hlA = *(const __nv_bfloat162*)(Hpl + iA);
            __nv_bfloat162 hhB = *(const __nv_bfloat162*)(Hph + iB);
            __nv_bfloat162 hlB = *(const __nv_bfloat162*)(Hpl + iB);
            float d0 = acc[ni][0] * sig_from_h(__bfloat162float(hhA.x) + __bfloat162float(hlA.x));
            float d1 = acc[ni][1] * sig_from_h(__bfloat162float(hhA.y) + __bfloat162float(hlA.y));
            float d2 = acc[ni][2] * sig_from_h(__bfloat162float(hhB.x) + __bfloat162float(hlB.x));
            float d3 = acc[ni][3] * sig_from_h(__bfloat162float(hhB.y) + __bfloat162float(hlB.y));
            split_store2(Oh, Ol, iA, d0, d1);
            split_store2(Oh, Ol, iB, d2, d3);
        }
    } else {
        float* G = g_buf + O_G;
#pragma unroll
        for (int ni = 0; ni < 4; ni++) {
            int mA = m0 + wm + l4;
            int np = nb + wn + ni * 8 + l2;
            size_t gA = (size_t)mA * Zd + np, gB = gA + 8ull * Zd;
            float2 bA, bB;
            if (FIRSTG) {
                float2 w2 = *(const float2*)(wx_out + np);
                bA = w2; bB = w2;
            } else {
                bA = *(const float2*)(G + gA);
                bB = *(const float2*)(G + gB);
            }
            float2 oA, oB;
            oA.x = bA.x + acc[ni][0]; oA.y = bA.y + acc[ni][1];
            oB.x = bB.x + acc[ni][2]; oB.y = bB.y + acc[ni][3];
            *(float2*)(G + gA) = oA;
            *(float2*)(G + gB) = oB;
        }
    }
}

// ---------------------------------------------------------------------------
// Final backward + Adam
// ---------------------------------------------------------------------------
__global__ void __launch_bounds__(GTHR, 2) kbwdin(
    const __nv_bfloat16* __restrict__ Dh, const __nv_bfloat16* __restrict__ Dl,
    const __nv_bfloat16* __restrict__ WTh, const __nv_bfloat16* __restrict__ WTl,
    float* __restrict__ Z, __nv_bfloat16* __restrict__ Zh, __nv_bfloat16* __restrict__ Zl,
    float bc1, float bc2)
{
    extern __shared__ __align__(16) char dsm[];
    uint32_t smbase = (uint32_t)__cvta_generic_to_shared(dsm);
    const int tid = threadIdx.x, lane = tid & 31, wid = tid >> 5;
    const int wm = (wid >> 1) * 16, wn = (wid & 1) * 32;
    const int m0 = blockIdx.y * BM, n0 = blockIdx.x * BN;

    float acc[4][4];
#pragma unroll
    for (int b = 0; b < 4; b++)
#pragma unroll
        for (int d = 0; d < 4; d++) acc[b][d] = 0.f;

    gemm_tn(acc, smbase, Dh, Dl, Hd, WTh, WTl, Hd, Hd / BKT,
            m0, n0, tid, lane, wm, wn);

    const float* G = g_buf + O_G;
    float* Mm = g_buf + O_M;
    float* Vv = g_buf + O_V;
    const int l4 = lane >> 2, l2 = (lane & 3) * 2;
#pragma unroll
    for (int ni = 0; ni < 4; ni++) {
        int mA = m0 + wm + l4;
        int np = n0 + wn + ni * 8 + l2;
        size_t idx[2];
        idx[0] = (size_t)mA * Zd + np;
        idx[1] = idx[0] + 8ull * Zd;
#pragma unroll
        for (int hh = 0; hh < 2; hh++) {
            size_t id = idx[hh];
            float g0 = G[id]     + acc[ni][hh * 2 + 0];
            float g1 = G[id + 1] + acc[ni][hh * 2 + 1];
            float2 m2 = *(const float2*)(Mm + id);
            float2 v2 = *(const float2*)(Vv + id);
            float nm0 = 0.9f * m2.x + 0.1f * g0;
            float nm1 = 0.9f * m2.y + 0.1f * g1;
            float nv0 = 0.999f * v2.x + 0.001f * g0 * g0;
            float nv1 = 0.999f * v2.y + 0.001f * g1 * g1;
            *(float2*)(Mm + id) = make_float2(nm0, nm1);
            *(float2*)(Vv + id) = make_float2(nv0, nv1);
            float2 z2 = *(const float2*)(Z + id);
            z2.x -= 0.01f * (nm0 * bc1) / (sqrtf(nv0 * bc2) + 1e-8f);
            z2.y -= 0.01f * (nm1 * bc1) / (sqrtf(nv1 * bc2) + 1e-8f);
            *(float2*)(Z + id) = z2;
            split_store2(Zh, Zl, id, z2.x, z2.y);
        }
    }
}

// ---------------------------------------------------------------------------
// Host driver
// ---------------------------------------------------------------------------
extern "C" void kernel_launch(void* const* d_in, const int* in_sizes, int n_in,
                              void* d_out, int out_size)
{
    (void)in_sizes; (void)n_in; (void)out_size;
    const float* x      = (const float*)d_in[0];
    const float* u      = (const float*)d_in[1];
    const float* W_in   = (const float*)d_in[2];
    const float* b_in   = (const float*)d_in[3];
    const float* Wzs    = (const float*)d_in[4];
    const float* Wxs    = (const float*)d_in[5];
    const float* bs     = (const float*)d_in[6];
    const float* wz_out = (const float*)d_in[7];
    const float* wx_out = (const float*)d_in[8];
    float* z = (float*)d_out;

    float* buf = nullptr;
    { void* p = nullptr; cudaGetSymbolAddress(&p, g_buf); buf = (float*)p; }
    __nv_bfloat16* bb = nullptr;
    { void* p = nullptr; cudaGetSymbolAddress(&p, g_bf); bb = (__nv_bfloat16*)p; }

    float* C = buf + O_C;

    static bool attr_done = false;
    if (!attr_done) {
        cudaFuncSetAttribute(kfwd<0>, cudaFuncAttributeMaxDynamicSharedMemorySize, SMEM_BYTES);
        cudaFuncSetAttribute(kfwd<1>, cudaFuncAttributeMaxDynamicSharedMemorySize, SMEM_BYTES);
        cudaFuncSetAttribute(kfwd<2>, cudaFuncAttributeMaxDynamicSharedMemorySize, SMEM_BYTES);
        cudaFuncSetAttribute(kbwd<true>,  cudaFuncAttributeMaxDynamicSharedMemorySize, SMEM_BYTES);
        cudaFuncSetAttribute(kbwd<false>, cudaFuncAttributeMaxDynamicSharedMemorySize, SMEM_BYTES);
        cudaFuncSetAttribute(kbwdin, cudaFuncAttributeMaxDynamicSharedMemorySize, SMEM_BYTES);
        attr_done = true;
    }

    kprep<<<2048, 512>>>(Wzs, wz_out, W_in, Wxs, z);
    kpre<<<dim3(Hd / BN, Bsz / BM, 4), NTHR>>>(x, u, W_in, b_in, Wxs, bs);

    const dim3 gF(Hd / BN, Bsz / BM);            // 13 x 32
    const dim3 gB((Hd + Zd) / BN, Bsz / BM);     // 17 x 32
    const dim3 gI(Zd / BN, Bsz / BM);            // 4 x 32
    const dim3 blk(GTHR);

    __nv_bfloat16 *Zh = bb + OB_Z_H, *Zl = bb + OB_Z_L;
    __nv_bfloat16 *DAh = bb + OB_DA_H, *DAl = bb + OB_DA_L;
    __nv_bfloat16 *DBh = bb + OB_DB_H, *DBl = bb + OB_DB_L;

    for (int t = 0; t < NSTEPS; t++) {
        kfwd<0><<<gF, blk, SMEM_BYTES>>>(
            Zh, Zl, bb + OB_WINZ_H, bb + OB_WINZ_L,
            (const __nv_bfloat16*)nullptr, (const __nv_bfloat16*)nullptr,
            (const __nv_bfloat16*)nullptr, (const __nv_bfloat16*)nullptr,
            C, bb + OB_H_H, bb + OB_H_L);
        for (int l = 0; l < 3; l++) {
            __nv_bfloat16* Ah = bb + OB_H_H + (size_t)l * BH;
            __nv_bfloat16* Al = bb + OB_H_L + (size_t)l * BH;
            __nv_bfloat16* Oh = (l < 2) ? bb + OB_H_H + (size_t)(l + 1) * BH : DAh;
            __nv_bfloat16* Ol = (l < 2) ? bb + OB_H_L + (size_t)(l + 1) * BH : DAl;
            if (l < 2)
                kfwd<1><<<gF, blk, SMEM_BYTES>>>(
                    Ah, Al, bb + OB_SWZF_H + (size_t)l * HH, bb + OB_SWZF_L + (size_t)l * HH,
                    Zh, Zl, bb + OB_WXZ_H + (size_t)l * (Hd * Zd), bb + OB_WXZ_L + (size_t)l * (Hd * Zd),
                    C + (size_t)(l + 1) * BH, Oh, Ol);
            else
                kfwd<2><<<gF, blk, SMEM_BYTES>>>(
                    Ah, Al, bb + OB_SWZF_H + (size_t)l * HH, bb + OB_SWZF_L + (size_t)l * HH,
                    Zh, Zl, bb + OB_WXZ_H + (size_t)l * (Hd * Zd), bb + OB_WXZ_L + (size_t)l * (Hd * Zd),
                    C + (size_t)(l + 1) * BH, Oh, Ol);
        }
        kbwd<true><<<gB, blk, SMEM_BYTES>>>(
            DAh, DAl,
            bb + OB_SWZT_H + 2ull * HH, bb + OB_SWZT_L + 2ull * HH,
            bb + OB_WXZT_H + 2ull * (Zd * Hd), bb + OB_WXZT_L + 2ull * (Zd * Hd),
            bb + OB_H_H + 2ull * BH, bb + OB_H_L + 2ull * BH,
            DBh, DBl, wx_out);
        kbwd<false><<<gB, blk, SMEM_BYTES>>>(
            DBh, DBl,
            bb + OB_SWZT_H + 1ull * HH, bb + OB_SWZT_L + 1ull * HH,
            bb + OB_WXZT_H + 1ull * (Zd * Hd), bb + OB_WXZT_L + 1ull * (Zd * Hd),
            bb + OB_H_H + 1ull * BH, bb + OB_H_L + 1ull * BH,
            DAh, DAl, wx_out);
        kbwd<false><<<gB, blk, SMEM_BYTES>>>(
            DAh, DAl,
            bb + OB_SWZT_H, bb + OB_SWZT_L,
            bb + OB_WXZT_H, bb + OB_WXZT_L,
            bb + OB_H_H, bb + OB_H_L,
            DBh, DBl, wx_out);
        double p1 = 1.0, p2 = 1.0;
        for (int q = 0; q <= t; q++) { p1 *= 0.9; p2 *= 0.999; }
        float bc1 = (float)(1.0 / (1.0 - p1));
        float bc2 = (float)(1.0 / (1.0 - p2));
        kbwdin<<<gI, blk, SMEM_BYTES>>>(
            DBh, DBl, bb + OB_WINZT_H, bb + OB_WINZT_L,
            z, Zh, Zl, bc1, bc2);
    }
}

// round 10
// speedup vs baseline: 1.5687x; 1.5492x over previous
#include <cuda_runtime.h>
#include <cuda_fp16.h>
#include <math.h>
#include <stdint.h>

// ---------------------------------------------------------------------------
// KoopmanPhiICNN encode, R10: fp16 2-pass mma.sync GEMMs (A single fp16,
// B split hi/lo). Exact power-of-2 scaling:
//   activations h, z stored x2^-5; fwd weights x2^5 -> fwd accs unscaled.
//   gradients: stored_d3 x1, d2 x1, d1 x2^-4, d0 x2^-13, compensated exactly
//   in downstream epilogues (rs = ratio, gs = g-path unscale).
// R6-proven 3-stage cp.async pipeline, 256 threads, 32x32 warp tiles.
// ---------------------------------------------------------------------------

#define Bsz 4096
#define Hd  832
#define Zd  256
#define BH  (Bsz*Hd)
#define HH  (Hd*Hd)
#define BZ  (Bsz*Zd)
#define NSTEPS 64

#define BM 128
#define BN 64
#define BKT 32
#define BK 16
#define NTHR 256
#define NSTAGE 3

#define SCL   32.0f      // weight pre-scale (2^5)
#define ISCL  0.03125f   // activation store scale (2^-5)

// ---- fp32 scratch ----
#define O_SWZO 0ull
#define O_C    (O_SWZO + 1024ull)
#define O_G    (O_C + 4ull*BH)
#define O_M    (O_G + (unsigned long long)BZ)
#define O_V    (O_M + (unsigned long long)BZ)
#define TOTALF (O_V + (unsigned long long)BZ)
__device__ __align__(16) float g_buf[TOTALF];

// ---- fp16 scratch ----
#define SZ_WINZ  (832ull*256ull)
#define SZ_WXZ   (3ull*832ull*256ull)
#define SZ_SWZ   (3ull*(unsigned long long)HH)
#define OB_WINZ_H  0ull
#define OB_WINZ_L  (OB_WINZ_H + SZ_WINZ)
#define OB_WXZ_H   (OB_WINZ_L + SZ_WINZ)
#define OB_WXZ_L   (OB_WXZ_H + SZ_WXZ)
#define OB_SWZF_H  (OB_WXZ_L + SZ_WXZ)
#define OB_SWZF_L  (OB_SWZF_H + SZ_SWZ)
#define OB_SWZT_H  (OB_SWZF_L + SZ_SWZ)
#define OB_SWZT_L  (OB_SWZT_H + SZ_SWZ)
#define OB_WXZT_H  (OB_SWZT_L + SZ_SWZ)
#define OB_WXZT_L  (OB_WXZT_H + SZ_WXZ)
#define OB_WINZT_H (OB_WXZT_L + SZ_WXZ)
#define OB_WINZT_L (OB_WINZT_H + SZ_WINZ)
#define OB_H       (OB_WINZT_L + SZ_WINZ)
#define OB_DA      (OB_H + 3ull*BH)
#define OB_DB      (OB_DA + (unsigned long long)BH)
#define OB_Z       (OB_DB + (unsigned long long)BH)
#define TOTALH     (OB_Z + (unsigned long long)BZ)
__device__ __align__(16) __half g_hf[TOTALH];

__device__ __forceinline__ float sp_(float x) {
    return fmaxf(x, 0.f) + log1pf(expf(-fabsf(x)));
}
__device__ __forceinline__ float sig_(float x) { return 1.f / (1.f + expf(-x)); }
__device__ __forceinline__ float sig_from_h(float h) { return -expm1f(-h); }

__device__ __forceinline__ void hsplit(float v, __half& h, __half& l) {
    __half hh = __float2half_rn(v);
    h = hh;
    l = __float2half_rn(v - __half2float(hh));
}

// ---------------------------------------------------------------------------
// TN tensor-core GEMM core: C[128,64] += A[128,K]*(Bh+Bl)[64,K]^T, fp16 x2
// ---------------------------------------------------------------------------
#define SA 40
#define OFF_A  0
#define OFF_BH (128*SA)
#define OFF_BL (128*SA + 64*SA)
#define STAGE_H (128*SA + 2*64*SA)          // 10240 halves = 20480 B
#define SMEM_BYTES (NSTAGE*2*STAGE_H)       // 61440 B

__device__ __forceinline__ void ldsm4(uint32_t* r, uint32_t addr) {
    asm volatile("ldmatrix.sync.aligned.m8n8.x4.shared.b16 {%0,%1,%2,%3}, [%4];\n"
        : "=r"(r[0]), "=r"(r[1]), "=r"(r[2]), "=r"(r[3]) : "r"(addr));
}
__device__ __forceinline__ void mmah(float* c, const uint32_t* a, uint32_t b0, uint32_t b1) {
    asm volatile("mma.sync.aligned.m16n8k16.row.col.f32.f16.f16.f32 "
        "{%0,%1,%2,%3},{%4,%5,%6,%7},{%8,%9},{%0,%1,%2,%3};\n"
        : "+f"(c[0]), "+f"(c[1]), "+f"(c[2]), "+f"(c[3])
        : "r"(a[0]), "r"(a[1]), "r"(a[2]), "r"(a[3]), "r"(b0), "r"(b1));
}
__device__ __forceinline__ void cp16(uint32_t dst, const void* src) {
    asm volatile("cp.async.cg.shared.global [%0], [%1], 16;\n" :: "r"(dst), "l"(src));
}
__device__ __forceinline__ void cpcommit() { asm volatile("cp.async.commit_group;\n"); }
template<int N> __device__ __forceinline__ void cpwait() {
    asm volatile("cp.async.wait_group %0;\n" :: "n"(N));
}

__device__ __forceinline__ void ld_stage(uint32_t smst,
    const __half* __restrict__ A, int lda,
    const __half* __restrict__ Bh, const __half* __restrict__ Bl, int ldb,
    int m0, int n0, int k0, int tid)
{
#pragma unroll
    for (int h = 0; h < 2; h++) {
        int ch = tid + h * 256;
        int row = ch >> 2, kc = ch & 3;
        size_t go = (size_t)(m0 + row) * lda + k0 + kc * 8;
        uint32_t so = smst + 2 * (OFF_A + row * SA + kc * 8);
        cp16(so, A + go);
    }
    {
        int row = tid >> 2, kc = tid & 3;
        size_t go = (size_t)(n0 + row) * ldb + k0 + kc * 8;
        uint32_t so = smst + 2 * (OFF_BH + row * SA + kc * 8);
        cp16(so, Bh + go);
        cp16(so + 2 * (OFF_BL - OFF_BH), Bl + go);
    }
}

__device__ __forceinline__ void compute_stage(float acc[2][4][4], uint32_t smst,
                                              int lane, int wm, int wn)
{
#pragma unroll
    for (int kk = 0; kk < 2; kk++) {
        const int k16 = kk * 16;
        uint32_t a0[4], a1[4];
        {
            int arow = lane & 15;
            int akoff = k16 + ((lane >> 4) << 3);
            uint32_t ad = smst + 2 * ((wm + arow) * SA + akoff);
            ldsm4(a0, ad);
            ldsm4(a1, ad + 2 * 16 * SA);
        }
        uint32_t b0h[4], b1h[4], b0l[4], b1l[4];
        {
            int brow = ((lane >> 4) << 3) + (lane & 7);
            int bkoff = k16 + (((lane >> 3) & 1) << 3);
            uint32_t bd = smst + 2 * (OFF_BH + (wn + brow) * SA + bkoff);
            ldsm4(b0h, bd);
            ldsm4(b1h, bd + 2 * 16 * SA);
            ldsm4(b0l, bd + 2 * (OFF_BL - OFF_BH));
            ldsm4(b1l, bd + 2 * (OFF_BL - OFF_BH) + 2 * 16 * SA);
        }
#pragma unroll
        for (int mi = 0; mi < 2; mi++) {
            const uint32_t* Af = mi ? a1 : a0;
#pragma unroll
            for (int ni = 0; ni < 4; ni++) {
                const uint32_t* Bhf = (ni < 2) ? b0h : b1h;
                const uint32_t* Blf = (ni < 2) ? b0l : b1l;
                int h2 = (ni & 1) * 2;
                mmah(acc[mi][ni], Af, Bhf[h2], Bhf[h2 + 1]);
                mmah(acc[mi][ni], Af, Blf[h2], Blf[h2 + 1]);
            }
        }
    }
}

// R6-proven 3-stage pipeline: one barrier per stage, loads after compute.
__device__ __forceinline__ void gemm_tn(float acc[2][4][4], uint32_t smbase,
    const __half* A, int lda,
    const __half* Bh, const __half* Bl, int ldb,
    int kt, int m0, int n0, int tid, int lane, int wm, int wn)
{
    __syncthreads();   // previous users of smem done
    ld_stage(smbase, A, lda, Bh, Bl, ldb, m0, n0, 0, tid);
    cpcommit();
    if (kt > 1) ld_stage(smbase + 2 * STAGE_H, A, lda, Bh, Bl, ldb, m0, n0, BKT, tid);
    cpcommit();

    for (int t = 0; t < kt; t++) {
        cpwait<1>();
        __syncthreads();
        compute_stage(acc, smbase + (t % 3) * 2 * STAGE_H, lane, wm, wn);
        if (t + 2 < kt)
            ld_stage(smbase + ((t + 2) % 3) * 2 * STAGE_H,
                     A, lda, Bh, Bl, ldb, m0, n0, (t + 2) * BKT, tid);
        cpcommit();
    }
    cpwait<0>();
}

// ---------------------------------------------------------------------------
// fp32 SIMT kpre (runs once): c[s] = [x|u] @ W_s[:,256:]^T + bias_s
// ---------------------------------------------------------------------------
__device__ __forceinline__ void mm_compute(float acc[8][4],
    const float As[BK][BM + 4], const float Bs[BK][BN], int tx, int ty)
{
#pragma unroll
    for (int kk = 0; kk < BK; kk++) {
        float4 a0 = *reinterpret_cast<const float4*>(&As[kk][ty * 8]);
        float4 a1 = *reinterpret_cast<const float4*>(&As[kk][ty * 8 + 4]);
        float4 b  = *reinterpret_cast<const float4*>(&Bs[kk][tx * 4]);
        float av[8] = {a0.x, a0.y, a0.z, a0.w, a1.x, a1.y, a1.z, a1.w};
        float bv[4] = {b.x, b.y, b.z, b.w};
#pragma unroll
        for (int i = 0; i < 8; i++)
#pragma unroll
            for (int j = 0; j < 4; j++)
                acc[i][j] = fmaf(av[i], bv[j], acc[i][j]);
    }
}
__device__ __forceinline__ void st_nt(float As[BK][BM + 4], float Bs[BK][BN],
                                      int r, int c, float4 va0, float4 va1, float4 vb)
{
    As[c + 0][r] = va0.x; As[c + 1][r] = va0.y; As[c + 2][r] = va0.z; As[c + 3][r] = va0.w;
    As[c + 0][r + 64] = va1.x; As[c + 1][r + 64] = va1.y; As[c + 2][r + 64] = va1.z; As[c + 3][r + 64] = va1.w;
    Bs[c + 0][r] = vb.x; Bs[c + 1][r] = vb.y; Bs[c + 2][r] = vb.z; Bs[c + 3][r] = vb.w;
}

__global__ void __launch_bounds__(NTHR) kpre(
    const float* __restrict__ x, const float* __restrict__ u,
    const float* __restrict__ W_in, const float* __restrict__ b_in,
    const float* __restrict__ Wxs, const float* __restrict__ bs)
{
    __shared__ float As[2][BK][BM + 4];
    __shared__ float Bs[2][BK][BN];
    const int tid = threadIdx.x, tx = tid & 15, ty = tid >> 4;
    const int m0 = blockIdx.y * BM, n0 = blockIdx.x * BN;
    const int s = blockIdx.z;
    const float* W    = (s == 0) ? W_in : Wxs + (size_t)(s - 1) * HH;
    const float* bias = (s == 0) ? b_in : bs + (size_t)(s - 1) * Hd;
    float* Out = g_buf + O_C + (size_t)s * BH;

    float acc[8][4];
#pragma unroll
    for (int i = 0; i < 8; i++)
#pragma unroll
        for (int j = 0; j < 4; j++) acc[i][j] = 0.f;

    const int r = tid >> 2;
    const int c = (tid & 3) * 4;
    const int kt = 576 / BK;
    const float* Bp = W + (size_t)(n0 + r) * Hd + 256 + c;

    float4 va0, va1, vb;
    va0 = *reinterpret_cast<const float4*>(&x[(size_t)(m0 + r) * 512 + c]);
    va1 = *reinterpret_cast<const float4*>(&x[(size_t)(m0 + r + 64) * 512 + c]);
    vb  = *reinterpret_cast<const float4*>(Bp);
    __syncthreads();
    st_nt(As[0], Bs[0], r, c, va0, va1, vb);
    __syncthreads();

    for (int t = 0; t < kt; t++) {
        int buf = t & 1;
        if (t + 1 < kt) {
            int k = (t + 1) * BK + c;
            if (k < 512) {
                va0 = *reinterpret_cast<const float4*>(&x[(size_t)(m0 + r) * 512 + k]);
                va1 = *reinterpret_cast<const float4*>(&x[(size_t)(m0 + r + 64) * 512 + k]);
            } else {
                va0 = *reinterpret_cast<const float4*>(&u[(size_t)(m0 + r) * 64 + (k - 512)]);
                va1 = *reinterpret_cast<const float4*>(&u[(size_t)(m0 + r + 64) * 64 + (k - 512)]);
            }
            vb = *reinterpret_cast<const float4*>(Bp + (t + 1) * BK);
        }
        mm_compute(acc, As[buf], Bs[buf], tx, ty);
        if (t + 1 < kt) st_nt(As[buf ^ 1], Bs[buf ^ 1], r, c, va0, va1, vb);
        __syncthreads();
    }

    const float4 b4 = *reinterpret_cast<const float4*>(&bias[n0 + tx * 4]);
#pragma unroll
    for (int i = 0; i < 8; i++) {
        int m = m0 + ty * 8 + i;
        float4 o;
        o.x = acc[i][0] + b4.x; o.y = acc[i][1] + b4.y;
        o.z = acc[i][2] + b4.z; o.w = acc[i][3] + b4.w;
        *reinterpret_cast<float4*>(&Out[(size_t)m * Hd + n0 + tx * 4]) = o;
    }
}

// ---------------------------------------------------------------------------
// Prep: weight splits/transposes (scaled) + state init
// ---------------------------------------------------------------------------
__global__ void kprep(const float* __restrict__ Wzs, const float* __restrict__ wz_out,
                      const float* __restrict__ W_in, const float* __restrict__ Wxs,
                      float* __restrict__ Z)
{
    __half* hf = g_hf;
    float* SWZO = g_buf + O_SWZO;
    float* Mm = g_buf + O_M;
    float* Vv = g_buf + O_V;
    const int n = 3 * HH;
    for (int i = blockIdx.x * blockDim.x + threadIdx.x; i < n;
         i += gridDim.x * blockDim.x) {
        int l = i / HH, o = i - l * HH;
        int r = o / Hd, c = o - r * Hd;
        float w = sp_(Wzs[i]);
        hsplit(w * SCL, hf[OB_SWZF_H + i], hf[OB_SWZF_L + i]);
        size_t ti = (size_t)l * HH + (size_t)c * Hd + r;
        hsplit(w, hf[OB_SWZT_H + ti], hf[OB_SWZT_L + ti]);
        if (c < Zd) {
            float wx = Wxs[i] * SCL;
            size_t zi = (size_t)l * (Hd * Zd) + (size_t)r * Zd + c;
            hsplit(wx, hf[OB_WXZ_H + zi], hf[OB_WXZ_L + zi]);
            size_t zt = (size_t)l * (Zd * Hd) + (size_t)c * Hd + r;
            hsplit(wx, hf[OB_WXZT_H + zt], hf[OB_WXZT_L + zt]);
            if (l == 0) {
                float wi = W_in[o] * SCL;
                hsplit(wi, hf[OB_WINZ_H + (size_t)r * Zd + c],
                           hf[OB_WINZ_L + (size_t)r * Zd + c]);
                hsplit(wi, hf[OB_WINZT_H + (size_t)c * Hd + r],
                           hf[OB_WINZT_L + (size_t)c * Hd + r]);
            }
        }
        if (i < Hd) SWZO[i] = sp_(wz_out[i]);
        if (i < BZ) {
            Z[i] = 0.f; Mm[i] = 0.f; Vv[i] = 0.f;
            hf[OB_Z + i] = __float2half_rn(0.f);
        }
    }
}

// ---------------------------------------------------------------------------
// Forward: MODE 0 input layer, MODE 1 hidden (store h x2^-5),
//          MODE 2 hidden+final (store d3 UNSCALED).
// ---------------------------------------------------------------------------
template<int MODE>
__global__ void __launch_bounds__(NTHR, 2) kfwd(
    const __half* __restrict__ A1, const __half* __restrict__ B1h, const __half* __restrict__ B1l,
    const __half* __restrict__ A2, const __half* __restrict__ B2h, const __half* __restrict__ B2l,
    const float* __restrict__ C0, __half* __restrict__ O)
{
    extern __shared__ __align__(16) char dsm[];
    uint32_t smbase = (uint32_t)__cvta_generic_to_shared(dsm);
    const int tid = threadIdx.x, lane = tid & 31, wid = tid >> 5;
    const int wm = (wid >> 1) * 32, wn = (wid & 1) * 32;
    const int m0 = blockIdx.y * BM, n0 = blockIdx.x * BN;

    float acc[2][4][4];
#pragma unroll
    for (int a = 0; a < 2; a++)
#pragma unroll
        for (int b = 0; b < 4; b++)
#pragma unroll
            for (int d = 0; d < 4; d++) acc[a][b][d] = 0.f;

    if (MODE == 0) {
        gemm_tn(acc, smbase, A1, Zd, B1h, B1l, Zd, Zd / BKT, m0, n0, tid, lane, wm, wn);
    } else {
        gemm_tn(acc, smbase, A1, Hd, B1h, B1l, Hd, Hd / BKT, m0, n0, tid, lane, wm, wn);
        gemm_tn(acc, smbase, A2, Zd, B2h, B2l, Zd, Zd / BKT, m0, n0, tid, lane, wm, wn);
    }

    const int l4 = lane >> 2, l2 = (lane & 3) * 2;
#pragma unroll
    for (int mi = 0; mi < 2; mi++)
#pragma unroll
    for (int ni = 0; ni < 4; ni++) {
        int mA = m0 + wm + mi * 16 + l4;
        int n  = n0 + wn + ni * 8 + l2;
        size_t iA = (size_t)mA * Hd + n, iB = iA + 8ull * Hd;
        float2 cA = *(const float2*)(C0 + iA);
        float2 cB = *(const float2*)(C0 + iB);
        float v0 = acc[mi][ni][0] + cA.x, v1 = acc[mi][ni][1] + cA.y;
        float v2 = acc[mi][ni][2] + cB.x, v3 = acc[mi][ni][3] + cB.y;
        if (MODE == 2) {
            const float* SWZO = g_buf + O_SWZO;
            float2 s2 = *(const float2*)(SWZO + n);
            v0 = s2.x * sig_(v0); v1 = s2.y * sig_(v1);
            v2 = s2.x * sig_(v2); v3 = s2.y * sig_(v3);
            *(__half2*)(O + iA) = __floats2half2_rn(v0, v1);        // d3 unscaled
            *(__half2*)(O + iB) = __floats2half2_rn(v2, v3);
        } else {
            v0 = sp_(v0); v1 = sp_(v1); v2 = sp_(v2); v3 = sp_(v3);
            *(__half2*)(O + iA) = __floats2half2_rn(v0 * ISCL, v1 * ISCL);
            *(__half2*)(O + iB) = __floats2half2_rn(v2 * ISCL, v3 * ISCL);
        }
    }
}

// ---------------------------------------------------------------------------
// Backward hidden layer.
//  d-path (n<832):  stored_dnext = (acc * sigma') * rs
//  g-path (n>=832): G += acc * gs     (FIRSTG: G = wx_out + acc*gs)
// ---------------------------------------------------------------------------
template<bool FIRSTG>
__global__ void __launch_bounds__(NTHR, 2) kbwd(
    const __half* __restrict__ D,
    const __half* __restrict__ STh, const __half* __restrict__ STl,
    const __half* __restrict__ XTh, const __half* __restrict__ XTl,
    const __half* __restrict__ Hp, __half* __restrict__ O,
    const float* __restrict__ wx_out, float rs, float gs)
{
    extern __shared__ __align__(16) char dsm[];
    uint32_t smbase = (uint32_t)__cvta_generic_to_shared(dsm);
    const int tid = threadIdx.x, lane = tid & 31, wid = tid >> 5;
    const int wm = (wid >> 1) * 32, wn = (wid & 1) * 32;
    const int m0 = blockIdx.y * BM, n0 = blockIdx.x * BN;
    const bool gpath = (n0 >= Hd);
    const int nb = gpath ? (n0 - Hd) : n0;

    float acc[2][4][4];
#pragma unroll
    for (int a = 0; a < 2; a++)
#pragma unroll
        for (int b = 0; b < 4; b++)
#pragma unroll
            for (int d = 0; d < 4; d++) acc[a][b][d] = 0.f;

    gemm_tn(acc, smbase, D, Hd,
            gpath ? XTh : STh, gpath ? XTl : STl, Hd, Hd / BKT,
            m0, nb, tid, lane, wm, wn);

    const int l4 = lane >> 2, l2 = (lane & 3) * 2;
    if (!gpath) {
#pragma unroll
        for (int mi = 0; mi < 2; mi++)
#pragma unroll
        for (int ni = 0; ni < 4; ni++) {
            int mA = m0 + wm + mi * 16 + l4;
            int n  = n0 + wn + ni * 8 + l2;
            size_t iA = (size_t)mA * Hd + n, iB = iA + 8ull * Hd;
            __half2 hA = *(const __half2*)(Hp + iA);
            __half2 hB = *(const __half2*)(Hp + iB);
            float d0 = acc[mi][ni][0] * sig_from_h(__half2float(hA.x) * SCL) * rs;
            float d1 = acc[mi][ni][1] * sig_from_h(__half2float(hA.y) * SCL) * rs;
            float d2 = acc[mi][ni][2] * sig_from_h(__half2float(hB.x) * SCL) * rs;
            float d3 = acc[mi][ni][3] * sig_from_h(__half2float(hB.y) * SCL) * rs;
            *(__half2*)(O + iA) = __floats2half2_rn(d0, d1);
            *(__half2*)(O + iB) = __floats2half2_rn(d2, d3);
        }
    } else {
        float* G = g_buf + O_G;
#pragma unroll
        for (int mi = 0; mi < 2; mi++)
#pragma unroll
        for (int ni = 0; ni < 4; ni++) {
            int mA = m0 + wm + mi * 16 + l4;
            int np = nb + wn + ni * 8 + l2;
            size_t gA = (size_t)mA * Zd + np, gB = gA + 8ull * Zd;
            float2 bA, bB;
            if (FIRSTG) {
                float2 w2 = *(const float2*)(wx_out + np);
                bA = w2; bB = w2;
            } else {
                bA = *(const float2*)(G + gA);
                bB = *(const float2*)(G + gB);
            }
            float2 oA, oB;
            oA.x = bA.x + acc[mi][ni][0] * gs; oA.y = bA.y + acc[mi][ni][1] * gs;
            oB.x = bB.x + acc[mi][ni][2] * gs; oB.y = bB.y + acc[mi][ni][3] * gs;
            *(float2*)(G + gA) = oA;
            *(float2*)(G + gB) = oB;
        }
    }
}

// ---------------------------------------------------------------------------
// Final backward + Adam: g = G + acc*gs; z fp32 master + fp16 copy x2^-5.
// ---------------------------------------------------------------------------
__global__ void __launch_bounds__(NTHR, 2) kbwdin(
    const __half* __restrict__ D,
    const __half* __restrict__ WTh, const __half* __restrict__ WTl,
    float* __restrict__ Z, __half* __restrict__ Zq,
    float bc1, float bc2, float gs)
{
    extern __shared__ __align__(16) char dsm[];
    uint32_t smbase = (uint32_t)__cvta_generic_to_shared(dsm);
    const int tid = threadIdx.x, lane = tid & 31, wid = tid >> 5;
    const int wm = (wid >> 1) * 32, wn = (wid & 1) * 32;
    const int m0 = blockIdx.y * BM, n0 = blockIdx.x * BN;

    float acc[2][4][4];
#pragma unroll
    for (int a = 0; a < 2; a++)
#pragma unroll
        for (int b = 0; b < 4; b++)
#pragma unroll
            for (int d = 0; d < 4; d++) acc[a][b][d] = 0.f;

    gemm_tn(acc, smbase, D, Hd, WTh, WTl, Hd, Hd / BKT,
            m0, n0, tid, lane, wm, wn);

    const float* G = g_buf + O_G;
    float* Mm = g_buf + O_M;
    float* Vv = g_buf + O_V;
    const int l4 = lane >> 2, l2 = (lane & 3) * 2;
#pragma unroll
    for (int mi = 0; mi < 2; mi++)
#pragma unroll
    for (int ni = 0; ni < 4; ni++) {
        int mA = m0 + wm + mi * 16 + l4;
        int np = n0 + wn + ni * 8 + l2;
        size_t idx[2];
        idx[0] = (size_t)mA * Zd + np;
        idx[1] = idx[0] + 8ull * Zd;
#pragma unroll
        for (int hh = 0; hh < 2; hh++) {
            size_t id = idx[hh];
            float g0 = G[id]     + acc[mi][ni][hh * 2 + 0] * gs;
            float g1 = G[id + 1] + acc[mi][ni][hh * 2 + 1] * gs;
            float2 m2 = *(const float2*)(Mm + id);
            float2 v2 = *(const float2*)(Vv + id);
            float nm0 = 0.9f * m2.x + 0.1f * g0;
            float nm1 = 0.9f * m2.y + 0.1f * g1;
            float nv0 = 0.999f * v2.x + 0.001f * g0 * g0;
            float nv1 = 0.999f * v2.y + 0.001f * g1 * g1;
            *(float2*)(Mm + id) = make_float2(nm0, nm1);
            *(float2*)(Vv + id) = make_float2(nv0, nv1);
            float2 z2 = *(const float2*)(Z + id);
            z2.x -= 0.01f * (nm0 * bc1) / (sqrtf(nv0 * bc2) + 1e-8f);
            z2.y -= 0.01f * (nm1 * bc1) / (sqrtf(nv1 * bc2) + 1e-8f);
            *(float2*)(Z + id) = z2;
            *(__half2*)(Zq + id) = __floats2half2_rn(z2.x * ISCL, z2.y * ISCL);
        }
    }
}

// ---------------------------------------------------------------------------
// Host driver
// ---------------------------------------------------------------------------
extern "C" void kernel_launch(void* const* d_in, const int* in_sizes, int n_in,
                              void* d_out, int out_size)
{
    (void)in_sizes; (void)n_in; (void)out_size;
    const float* x      = (const float*)d_in[0];
    const float* u      = (const float*)d_in[1];
    const float* W_in   = (const float*)d_in[2];
    const float* b_in   = (const float*)d_in[3];
    const float* Wzs    = (const float*)d_in[4];
    const float* Wxs    = (const float*)d_in[5];
    const float* bs     = (const float*)d_in[6];
    const float* wz_out = (const float*)d_in[7];
    const float* wx_out = (const float*)d_in[8];
    float* z = (float*)d_out;

    float* buf = nullptr;
    { void* p = nullptr; cudaGetSymbolAddress(&p, g_buf); buf = (float*)p; }
    __half* hb = nullptr;
    { void* p = nullptr; cudaGetSymbolAddress(&p, g_hf); hb = (__half*)p; }

    float* C = buf + O_C;

    static bool attr_done = false;
    if (!attr_done) {
        cudaFuncSetAttribute(kfwd<0>, cudaFuncAttributeMaxDynamicSharedMemorySize, SMEM_BYTES);
        cudaFuncSetAttribute(kfwd<1>, cudaFuncAttributeMaxDynamicSharedMemorySize, SMEM_BYTES);
        cudaFuncSetAttribute(kfwd<2>, cudaFuncAttributeMaxDynamicSharedMemorySize, SMEM_BYTES);
        cudaFuncSetAttribute(kbwd<true>,  cudaFuncAttributeMaxDynamicSharedMemorySize, SMEM_BYTES);
        cudaFuncSetAttribute(kbwd<false>, cudaFuncAttributeMaxDynamicSharedMemorySize, SMEM_BYTES);
        cudaFuncSetAttribute(kbwdin, cudaFuncAttributeMaxDynamicSharedMemorySize, SMEM_BYTES);
        attr_done = true;
    }

    kprep<<<2048, 512>>>(Wzs, wz_out, W_in, Wxs, z);
    kpre<<<dim3(Hd / BN, Bsz / BM, 4), NTHR>>>(x, u, W_in, b_in, Wxs, bs);

    const dim3 gF(Hd / BN, Bsz / BM);            // 13 x 32
    const dim3 gB((Hd + Zd) / BN, Bsz / BM);     // 17 x 32
    const dim3 gI(Zd / BN, Bsz / BM);            // 4 x 32
    const dim3 blk(NTHR);

    __half *Zq = hb + OB_Z;
    __half *DA = hb + OB_DA, *DB = hb + OB_DB;

    // Gradient scale plan (powers of 2, exact):
    //   s3 = 1, s2 = 1, s1 = 2^-4, s0 = 2^-13
    const float RS_32 = 1.0f;               // s2/s3
    const float RS_21 = 0.0625f;            // s1/s2 = 2^-4
    const float RS_10 = 0.001953125f;       // s0/s1 = 2^-9
    const float GS_3  = 0.03125f;           // 1/(32*s3) = 2^-5
    const float GS_2  = 0.03125f;           // 1/(32*s2) = 2^-5
    const float GS_1  = 0.5f;               // 1/(32*s1) = 2^-1
    const float GS_0  = 256.0f;             // 1/(32*s0) = 2^8

    for (int t = 0; t < NSTEPS; t++) {
        kfwd<0><<<gF, blk, SMEM_BYTES>>>(
            Zq, hb + OB_WINZ_H, hb + OB_WINZ_L,
            (const __half*)nullptr, (const __half*)nullptr, (const __half*)nullptr,
            C, hb + OB_H);
        for (int l = 0; l < 3; l++) {
            __half* Ain = hb + OB_H + (size_t)l * BH;
            __half* Out = (l < 2) ? hb + OB_H + (size_t)(l + 1) * BH : DA;
            if (l < 2)
                kfwd<1><<<gF, blk, SMEM_BYTES>>>(
                    Ain, hb + OB_SWZF_H + (size_t)l * HH, hb + OB_SWZF_L + (size_t)l * HH,
                    Zq, hb + OB_WXZ_H + (size_t)l * (Hd * Zd), hb + OB_WXZ_L + (size_t)l * (Hd * Zd),
                    C + (size_t)(l + 1) * BH, Out);
            else
                kfwd<2><<<gF, blk, SMEM_BYTES>>>(
                    Ain, hb + OB_SWZF_H + (size_t)l * HH, hb + OB_SWZF_L + (size_t)l * HH,
                    Zq, hb + OB_WXZ_H + (size_t)l * (Hd * Zd), hb + OB_WXZ_L + (size_t)l * (Hd * Zd),
                    C + (size_t)(l + 1) * BH, Out);
        }
        // d3(DA, s=1) -> d2(DB, s=1)
        kbwd<true><<<gB, blk, SMEM_BYTES>>>(
            DA,
            hb + OB_SWZT_H + 2ull * HH, hb + OB_SWZT_L + 2ull * HH,
            hb + OB_WXZT_H + 2ull * (Zd * Hd), hb + OB_WXZT_L + 2ull * (Zd * Hd),
            hb + OB_H + 2ull * BH, DB, wx_out, RS_32, GS_3);
        // d2(DB, s=1) -> d1(DA, s=2^-4)
        kbwd<false><<<gB, blk, SMEM_BYTES>>>(
            DB,
            hb + OB_SWZT_H + 1ull * HH, hb + OB_SWZT_L + 1ull * HH,
            hb + OB_WXZT_H + 1ull * (Zd * Hd), hb + OB_WXZT_L + 1ull * (Zd * Hd),
            hb + OB_H + 1ull * BH, DA, wx_out, RS_21, GS_2);
        // d1(DA, s=2^-4) -> d0(DB, s=2^-13)
        kbwd<false><<<gB, blk, SMEM_BYTES>>>(
            DA,
            hb + OB_SWZT_H, hb + OB_SWZT_L,
            hb + OB_WXZT_H, hb + OB_WXZT_L,
            hb + OB_H, DB, wx_out, RS_10, GS_1);
        double p1 = 1.0, p2 = 1.0;
        for (int q = 0; q <= t; q++) { p1 *= 0.9; p2 *= 0.999; }
        float bc1 = (float)(1.0 / (1.0 - p1));
        float bc2 = (float)(1.0 / (1.0 - p2));
        kbwdin<<<gI, blk, SMEM_BYTES>>>(
            DB, hb + OB_WINZT_H, hb + OB_WINZT_L,
            z, Zq, bc1, bc2, GS_0);
    }
}

// round 12
// speedup vs baseline: 2.1788x; 1.3889x over previous
#include <cuda_runtime.h>
#include <cuda_fp16.h>
#include <math.h>
#include <stdint.h>

// ---------------------------------------------------------------------------
// KoopmanPhiICNN encode, R12 (= R11 resubmitted after infra failure):
// single-pass fp16 mma.sync GEMMs (A and B both single fp16). Exact
// power-of-2 scaling: activations x2^-5, weights x2^5, per-layer gradient
// scales s3=1, s2=1, s1=2^-4, s0=2^-13 compensated exactly in epilogues.
// R6-proven 3-stage cp.async pipeline, 256 thr, 32x32 warp tile.
// ---------------------------------------------------------------------------

#define Bsz 4096
#define Hd  832
#define Zd  256
#define BH  (Bsz*Hd)
#define HH  (Hd*Hd)
#define BZ  (Bsz*Zd)
#define NSTEPS 64

#define BM 128
#define BN 64
#define BKT 32
#define BK 16
#define NTHR 256
#define NSTAGE 3

#define SCL   32.0f      // weight pre-scale (2^5)
#define ISCL  0.03125f   // activation store scale (2^-5)

// ---- fp32 scratch ----
#define O_SWZO 0ull
#define O_C    (O_SWZO + 1024ull)
#define O_G    (O_C + 4ull*BH)
#define O_M    (O_G + (unsigned long long)BZ)
#define O_V    (O_M + (unsigned long long)BZ)
#define TOTALF (O_V + (unsigned long long)BZ)
__device__ __align__(16) float g_buf[TOTALF];

// ---- fp16 scratch ----
#define SZ_WINZ  (832ull*256ull)
#define SZ_WXZ   (3ull*832ull*256ull)
#define SZ_SWZ   (3ull*(unsigned long long)HH)
#define OB_WINZ   0ull
#define OB_WXZ    (OB_WINZ + SZ_WINZ)
#define OB_SWZF   (OB_WXZ + SZ_WXZ)
#define OB_SWZT   (OB_SWZF + SZ_SWZ)
#define OB_WXZT   (OB_SWZT + SZ_SWZ)
#define OB_WINZT  (OB_WXZT + SZ_WXZ)
#define OB_H      (OB_WINZT + SZ_WINZ)
#define OB_DA     (OB_H + 3ull*BH)
#define OB_DB     (OB_DA + (unsigned long long)BH)
#define OB_Z      (OB_DB + (unsigned long long)BH)
#define TOTALH    (OB_Z + (unsigned long long)BZ)
__device__ __align__(16) __half g_hf[TOTALH];

__device__ __forceinline__ float sp_(float x) {
    return fmaxf(x, 0.f) + log1pf(expf(-fabsf(x)));
}
__device__ __forceinline__ float sig_(float x) { return 1.f / (1.f + expf(-x)); }
__device__ __forceinline__ float sig_from_h(float h) { return -expm1f(-h); }

// ---------------------------------------------------------------------------
// TN tensor-core GEMM core: C[128,64] += A[128,K]*B[64,K]^T, single fp16
// ---------------------------------------------------------------------------
#define SA 40
#define OFF_A  0
#define OFF_B  (128*SA)
#define STAGE_H ((128+64)*SA)               // 7680 halves = 15360 B
#define SMEM_BYTES (NSTAGE*2*STAGE_H)       // 46080 B

__device__ __forceinline__ void ldsm4(uint32_t* r, uint32_t addr) {
    asm volatile("ldmatrix.sync.aligned.m8n8.x4.shared.b16 {%0,%1,%2,%3}, [%4];\n"
        : "=r"(r[0]), "=r"(r[1]), "=r"(r[2]), "=r"(r[3]) : "r"(addr));
}
__device__ __forceinline__ void mmah(float* c, const uint32_t* a, uint32_t b0, uint32_t b1) {
    asm volatile("mma.sync.aligned.m16n8k16.row.col.f32.f16.f16.f32 "
        "{%0,%1,%2,%3},{%4,%5,%6,%7},{%8,%9},{%0,%1,%2,%3};\n"
        : "+f"(c[0]), "+f"(c[1]), "+f"(c[2]), "+f"(c[3])
        : "r"(a[0]), "r"(a[1]), "r"(a[2]), "r"(a[3]), "r"(b0), "r"(b1));
}
__device__ __forceinline__ void cp16(uint32_t dst, const void* src) {
    asm volatile("cp.async.cg.shared.global [%0], [%1], 16;\n" :: "r"(dst), "l"(src));
}
__device__ __forceinline__ void cpcommit() { asm volatile("cp.async.commit_group;\n"); }
template<int N> __device__ __forceinline__ void cpwait() {
    asm volatile("cp.async.wait_group %0;\n" :: "n"(N));
}

__device__ __forceinline__ void ld_stage(uint32_t smst,
    const __half* __restrict__ A, int lda,
    const __half* __restrict__ B, int ldb,
    int m0, int n0, int k0, int tid)
{
#pragma unroll
    for (int h = 0; h < 2; h++) {
        int ch = tid + h * 256;
        int row = ch >> 2, kc = ch & 3;
        size_t go = (size_t)(m0 + row) * lda + k0 + kc * 8;
        uint32_t so = smst + 2 * (OFF_A + row * SA + kc * 8);
        cp16(so, A + go);
    }
    {
        int row = tid >> 2, kc = tid & 3;
        size_t go = (size_t)(n0 + row) * ldb + k0 + kc * 8;
        uint32_t so = smst + 2 * (OFF_B + row * SA + kc * 8);
        cp16(so, B + go);
    }
}

__device__ __forceinline__ void compute_stage(float acc[2][4][4], uint32_t smst,
                                              int lane, int wm, int wn)
{
#pragma unroll
    for (int kk = 0; kk < 2; kk++) {
        const int k16 = kk * 16;
        uint32_t a0[4], a1[4];
        {
            int arow = lane & 15;
            int akoff = k16 + ((lane >> 4) << 3);
            uint32_t ad = smst + 2 * ((wm + arow) * SA + akoff);
            ldsm4(a0, ad);
            ldsm4(a1, ad + 2 * 16 * SA);
        }
        uint32_t b0[4], b1[4];
        {
            int brow = ((lane >> 4) << 3) + (lane & 7);
            int bkoff = k16 + (((lane >> 3) & 1) << 3);
            uint32_t bd = smst + 2 * (OFF_B + (wn + brow) * SA + bkoff);
            ldsm4(b0, bd);
            ldsm4(b1, bd + 2 * 16 * SA);
        }
#pragma unroll
        for (int mi = 0; mi < 2; mi++) {
            const uint32_t* Af = mi ? a1 : a0;
#pragma unroll
            for (int ni = 0; ni < 4; ni++) {
                const uint32_t* Bf = (ni < 2) ? b0 : b1;
                int h2 = (ni & 1) * 2;
                mmah(acc[mi][ni], Af, Bf[h2], Bf[h2 + 1]);
            }
        }
    }
}

// R6-proven 3-stage pipeline: one barrier per stage, loads after compute.
__device__ __forceinline__ void gemm_tn(float acc[2][4][4], uint32_t smbase,
    const __half* A, int lda,
    const __half* B, int ldb,
    int kt, int m0, int n0, int tid, int lane, int wm, int wn)
{
    __syncthreads();   // previous users of smem done
    ld_stage(smbase, A, lda, B, ldb, m0, n0, 0, tid);
    cpcommit();
    if (kt > 1) ld_stage(smbase + 2 * STAGE_H, A, lda, B, ldb, m0, n0, BKT, tid);
    cpcommit();

    for (int t = 0; t < kt; t++) {
        cpwait<1>();
        __syncthreads();
        compute_stage(acc, smbase + (t % 3) * 2 * STAGE_H, lane, wm, wn);
        if (t + 2 < kt)
            ld_stage(smbase + ((t + 2) % 3) * 2 * STAGE_H,
                     A, lda, B, ldb, m0, n0, (t + 2) * BKT, tid);
        cpcommit();
    }
    cpwait<0>();
}

// ---------------------------------------------------------------------------
// fp32 SIMT kpre (runs once): c[s] = [x|u] @ W_s[:,256:]^T + bias_s
// ---------------------------------------------------------------------------
__device__ __forceinline__ void mm_compute(float acc[8][4],
    const float As[BK][BM + 4], const float Bs[BK][BN], int tx, int ty)
{
#pragma unroll
    for (int kk = 0; kk < BK; kk++) {
        float4 a0 = *reinterpret_cast<const float4*>(&As[kk][ty * 8]);
        float4 a1 = *reinterpret_cast<const float4*>(&As[kk][ty * 8 + 4]);
        float4 b  = *reinterpret_cast<const float4*>(&Bs[kk][tx * 4]);
        float av[8] = {a0.x, a0.y, a0.z, a0.w, a1.x, a1.y, a1.z, a1.w};
        float bv[4] = {b.x, b.y, b.z, b.w};
#pragma unroll
        for (int i = 0; i < 8; i++)
#pragma unroll
            for (int j = 0; j < 4; j++)
                acc[i][j] = fmaf(av[i], bv[j], acc[i][j]);
    }
}
__device__ __forceinline__ void st_nt(float As[BK][BM + 4], float Bs[BK][BN],
                                      int r, int c, float4 va0, float4 va1, float4 vb)
{
    As[c + 0][r] = va0.x; As[c + 1][r] = va0.y; As[c + 2][r] = va0.z; As[c + 3][r] = va0.w;
    As[c + 0][r + 64] = va1.x; As[c + 1][r + 64] = va1.y; As[c + 2][r + 64] = va1.z; As[c + 3][r + 64] = va1.w;
    Bs[c + 0][r] = vb.x; Bs[c + 1][r] = vb.y; Bs[c + 2][r] = vb.z; Bs[c + 3][r] = vb.w;
}

__global__ void __launch_bounds__(NTHR) kpre(
    const float* __restrict__ x, const float* __restrict__ u,
    const float* __restrict__ W_in, const float* __restrict__ b_in,
    const float* __restrict__ Wxs, const float* __restrict__ bs)
{
    __shared__ float As[2][BK][BM + 4];
    __shared__ float Bs[2][BK][BN];
    const int tid = threadIdx.x, tx = tid & 15, ty = tid >> 4;
    const int m0 = blockIdx.y * BM, n0 = blockIdx.x * BN;
    const int s = blockIdx.z;
    const float* W    = (s == 0) ? W_in : Wxs + (size_t)(s - 1) * HH;
    const float* bias = (s == 0) ? b_in : bs + (size_t)(s - 1) * Hd;
    float* Out = g_buf + O_C + (size_t)s * BH;

    float acc[8][4];
#pragma unroll
    for (int i = 0; i < 8; i++)
#pragma unroll
        for (int j = 0; j < 4; j++) acc[i][j] = 0.f;

    const int r = tid >> 2;
    const int c = (tid & 3) * 4;
    const int kt = 576 / BK;
    const float* Bp = W + (size_t)(n0 + r) * Hd + 256 + c;

    float4 va0, va1, vb;
    va0 = *reinterpret_cast<const float4*>(&x[(size_t)(m0 + r) * 512 + c]);
    va1 = *reinterpret_cast<const float4*>(&x[(size_t)(m0 + r + 64) * 512 + c]);
    vb  = *reinterpret_cast<const float4*>(Bp);
    __syncthreads();
    st_nt(As[0], Bs[0], r, c, va0, va1, vb);
    __syncthreads();

    for (int t = 0; t < kt; t++) {
        int buf = t & 1;
        if (t + 1 < kt) {
            int k = (t + 1) * BK + c;
            if (k < 512) {
                va0 = *reinterpret_cast<const float4*>(&x[(size_t)(m0 + r) * 512 + k]);
                va1 = *reinterpret_cast<const float4*>(&x[(size_t)(m0 + r + 64) * 512 + k]);
            } else {
                va0 = *reinterpret_cast<const float4*>(&u[(size_t)(m0 + r) * 64 + (k - 512)]);
                va1 = *reinterpret_cast<const float4*>(&u[(size_t)(m0 + r + 64) * 64 + (k - 512)]);
            }
            vb = *reinterpret_cast<const float4*>(Bp + (t + 1) * BK);
        }
        mm_compute(acc, As[buf], Bs[buf], tx, ty);
        if (t + 1 < kt) st_nt(As[buf ^ 1], Bs[buf ^ 1], r, c, va0, va1, vb);
        __syncthreads();
    }

    const float4 b4 = *reinterpret_cast<const float4*>(&bias[n0 + tx * 4]);
#pragma unroll
    for (int i = 0; i < 8; i++) {
        int m = m0 + ty * 8 + i;
        float4 o;
        o.x = acc[i][0] + b4.x; o.y = acc[i][1] + b4.y;
        o.z = acc[i][2] + b4.z; o.w = acc[i][3] + b4.w;
        *reinterpret_cast<float4*>(&Out[(size_t)m * Hd + n0 + tx * 4]) = o;
    }
}

// ---------------------------------------------------------------------------
// Prep: scaled single-fp16 weight copies/transposes + state init
// ---------------------------------------------------------------------------
__global__ void kprep(const float* __restrict__ Wzs, const float* __restrict__ wz_out,
                      const float* __restrict__ W_in, const float* __restrict__ Wxs,
                      float* __restrict__ Z)
{
    __half* hf = g_hf;
    float* SWZO = g_buf + O_SWZO;
    float* Mm = g_buf + O_M;
    float* Vv = g_buf + O_V;
    const int n = 3 * HH;
    for (int i = blockIdx.x * blockDim.x + threadIdx.x; i < n;
         i += gridDim.x * blockDim.x) {
        int l = i / HH, o = i - l * HH;
        int r = o / Hd, c = o - r * Hd;
        float w = sp_(Wzs[i]);
        hf[OB_SWZF + i] = __float2half_rn(w * SCL);
        size_t ti = (size_t)l * HH + (size_t)c * Hd + r;
        hf[OB_SWZT + ti] = __float2half_rn(w);
        if (c < Zd) {
            float wx = Wxs[i] * SCL;
            size_t zi = (size_t)l * (Hd * Zd) + (size_t)r * Zd + c;
            hf[OB_WXZ + zi] = __float2half_rn(wx);
            size_t zt = (size_t)l * (Zd * Hd) + (size_t)c * Hd + r;
            hf[OB_WXZT + zt] = __float2half_rn(wx);
            if (l == 0) {
                float wi = W_in[o] * SCL;
                hf[OB_WINZ + (size_t)r * Zd + c] = __float2half_rn(wi);
                hf[OB_WINZT + (size_t)c * Hd + r] = __float2half_rn(wi);
            }
        }
        if (i < Hd) SWZO[i] = sp_(wz_out[i]);
        if (i < BZ) {
            Z[i] = 0.f; Mm[i] = 0.f; Vv[i] = 0.f;
            hf[OB_Z + i] = __float2half_rn(0.f);
        }
    }
}

// ---------------------------------------------------------------------------
// Forward: MODE 0 input layer, MODE 1 hidden (store h x2^-5),
//          MODE 2 hidden+final (store d3 unscaled).
// ---------------------------------------------------------------------------
template<int MODE>
__global__ void __launch_bounds__(NTHR, 2) kfwd(
    const __half* __restrict__ A1, const __half* __restrict__ B1,
    const __half* __restrict__ A2, const __half* __restrict__ B2,
    const float* __restrict__ C0, __half* __restrict__ O)
{
    extern __shared__ __align__(16) char dsm[];
    uint32_t smbase = (uint32_t)__cvta_generic_to_shared(dsm);
    const int tid = threadIdx.x, lane = tid & 31, wid = tid >> 5;
    const int wm = (wid >> 1) * 32, wn = (wid & 1) * 32;
    const int m0 = blockIdx.y * BM, n0 = blockIdx.x * BN;

    float acc[2][4][4];
#pragma unroll
    for (int a = 0; a < 2; a++)
#pragma unroll
        for (int b = 0; b < 4; b++)
#pragma unroll
            for (int d = 0; d < 4; d++) acc[a][b][d] = 0.f;

    if (MODE == 0) {
        gemm_tn(acc, smbase, A1, Zd, B1, Zd, Zd / BKT, m0, n0, tid, lane, wm, wn);
    } else {
        gemm_tn(acc, smbase, A1, Hd, B1, Hd, Hd / BKT, m0, n0, tid, lane, wm, wn);
        gemm_tn(acc, smbase, A2, Zd, B2, Zd, Zd / BKT, m0, n0, tid, lane, wm, wn);
    }

    const int l4 = lane >> 2, l2 = (lane & 3) * 2;
#pragma unroll
    for (int mi = 0; mi < 2; mi++)
#pragma unroll
    for (int ni = 0; ni < 4; ni++) {
        int mA = m0 + wm + mi * 16 + l4;
        int n  = n0 + wn + ni * 8 + l2;
        size_t iA = (size_t)mA * Hd + n, iB = iA + 8ull * Hd;
        float2 cA = *(const float2*)(C0 + iA);
        float2 cB = *(const float2*)(C0 + iB);
        float v0 = acc[mi][ni][0] + cA.x, v1 = acc[mi][ni][1] + cA.y;
        float v2 = acc[mi][ni][2] + cB.x, v3 = acc[mi][ni][3] + cB.y;
        if (MODE == 2) {
            const float* SWZO = g_buf + O_SWZO;
            float2 s2 = *(const float2*)(SWZO + n);
            v0 = s2.x * sig_(v0); v1 = s2.y * sig_(v1);
            v2 = s2.x * sig_(v2); v3 = s2.y * sig_(v3);
            *(__half2*)(O + iA) = __floats2half2_rn(v0, v1);
            *(__half2*)(O + iB) = __floats2half2_rn(v2, v3);
        } else {
            v0 = sp_(v0); v1 = sp_(v1); v2 = sp_(v2); v3 = sp_(v3);
            *(__half2*)(O + iA) = __floats2half2_rn(v0 * ISCL, v1 * ISCL);
            *(__half2*)(O + iB) = __floats2half2_rn(v2 * ISCL, v3 * ISCL);
        }
    }
}

// ---------------------------------------------------------------------------
// Backward hidden layer.
//  d-path (n<832):  stored_dnext = (acc * sigma') * rs
//  g-path (n>=832): G += acc * gs     (FIRSTG: G = wx_out + acc*gs)
// ---------------------------------------------------------------------------
template<bool FIRSTG>
__global__ void __launch_bounds__(NTHR, 2) kbwd(
    const __half* __restrict__ D,
    const __half* __restrict__ ST, const __half* __restrict__ XT,
    const __half* __restrict__ Hp, __half* __restrict__ O,
    const float* __restrict__ wx_out, float rs, float gs)
{
    extern __shared__ __align__(16) char dsm[];
    uint32_t smbase = (uint32_t)__cvta_generic_to_shared(dsm);
    const int tid = threadIdx.x, lane = tid & 31, wid = tid >> 5;
    const int wm = (wid >> 1) * 32, wn = (wid & 1) * 32;
    const int m0 = blockIdx.y * BM, n0 = blockIdx.x * BN;
    const bool gpath = (n0 >= Hd);
    const int nb = gpath ? (n0 - Hd) : n0;

    float acc[2][4][4];
#pragma unroll
    for (int a = 0; a < 2; a++)
#pragma unroll
        for (int b = 0; b < 4; b++)
#pragma unroll
            for (int d = 0; d < 4; d++) acc[a][b][d] = 0.f;

    gemm_tn(acc, smbase, D, Hd, gpath ? XT : ST, Hd, Hd / BKT,
            m0, nb, tid, lane, wm, wn);

    const int l4 = lane >> 2, l2 = (lane & 3) * 2;
    if (!gpath) {
#pragma unroll
        for (int mi = 0; mi < 2; mi++)
#pragma unroll
        for (int ni = 0; ni < 4; ni++) {
            int mA = m0 + wm + mi * 16 + l4;
            int n  = n0 + wn + ni * 8 + l2;
            size_t iA = (size_t)mA * Hd + n, iB = iA + 8ull * Hd;
            __half2 hA = *(const __half2*)(Hp + iA);
            __half2 hB = *(const __half2*)(Hp + iB);
            float d0 = acc[mi][ni][0] * sig_from_h(__half2float(hA.x) * SCL) * rs;
            float d1 = acc[mi][ni][1] * sig_from_h(__half2float(hA.y) * SCL) * rs;
            float d2 = acc[mi][ni][2] * sig_from_h(__half2float(hB.x) * SCL) * rs;
            float d3 = acc[mi][ni][3] * sig_from_h(__half2float(hB.y) * SCL) * rs;
            *(__half2*)(O + iA) = __floats2half2_rn(d0, d1);
            *(__half2*)(O + iB) = __floats2half2_rn(d2, d3);
        }
    } else {
        float* G = g_buf + O_G;
#pragma unroll
        for (int mi = 0; mi < 2; mi++)
#pragma unroll
        for (int ni = 0; ni < 4; ni++) {
            int mA = m0 + wm + mi * 16 + l4;
            int np = nb + wn + ni * 8 + l2;
            size_t gA = (size_t)mA * Zd + np, gB = gA + 8ull * Zd;
            float2 bA, bB;
            if (FIRSTG) {
                float2 w2 = *(const float2*)(wx_out + np);
                bA = w2; bB = w2;
            } else {
                bA = *(const float2*)(G + gA);
                bB = *(const float2*)(G + gB);
            }
            float2 oA, oB;
            oA.x = bA.x + acc[mi][ni][0] * gs; oA.y = bA.y + acc[mi][ni][1] * gs;
            oB.x = bB.x + acc[mi][ni][2] * gs; oB.y = bB.y + acc[mi][ni][3] * gs;
            *(float2*)(G + gA) = oA;
            *(float2*)(G + gB) = oB;
        }
    }
}

// ---------------------------------------------------------------------------
// Final backward + Adam: g = G + acc*gs; z fp32 master + fp16 copy x2^-5.
// ---------------------------------------------------------------------------
__global__ void __launch_bounds__(NTHR, 2) kbwdin(
    const __half* __restrict__ D, const __half* __restrict__ WT,
    float* __restrict__ Z, __half* __restrict__ Zq,
    float bc1, float bc2, float gs)
{
    extern __shared__ __align__(16) char dsm[];
    uint32_t smbase = (uint32_t)__cvta_generic_to_shared(dsm);
    const int tid = threadIdx.x, lane = tid & 31, wid = tid >> 5;
    const int wm = (wid >> 1) * 32, wn = (wid & 1) * 32;
    const int m0 = blockIdx.y * BM, n0 = blockIdx.x * BN;

    float acc[2][4][4];
#pragma unroll
    for (int a = 0; a < 2; a++)
#pragma unroll
        for (int b = 0; b < 4; b++)
#pragma unroll
            for (int d = 0; d < 4; d++) acc[a][b][d] = 0.f;

    gemm_tn(acc, smbase, D, Hd, WT, Hd, Hd / BKT, m0, n0, tid, lane, wm, wn);

    const float* G = g_buf + O_G;
    float* Mm = g_buf + O_M;
    float* Vv = g_buf + O_V;
    const int l4 = lane >> 2, l2 = (lane & 3) * 2;
#pragma unroll
    for (int mi = 0; mi < 2; mi++)
#pragma unroll
    for (int ni = 0; ni < 4; ni++) {
        int mA = m0 + wm + mi * 16 + l4;
        int np = n0 + wn + ni * 8 + l2;
        size_t idx[2];
        idx[0] = (size_t)mA * Zd + np;
        idx[1] = idx[0] + 8ull * Zd;
#pragma unroll
        for (int hh = 0; hh < 2; hh++) {
            size_t id = idx[hh];
            float g0 = G[id]     + acc[mi][ni][hh * 2 + 0] * gs;
            float g1 = G[id + 1] + acc[mi][ni][hh * 2 + 1] * gs;
            float2 m2 = *(const float2*)(Mm + id);
            float2 v2 = *(const float2*)(Vv + id);
            float nm0 = 0.9f * m2.x + 0.1f * g0;
            float nm1 = 0.9f * m2.y + 0.1f * g1;
            float nv0 = 0.999f * v2.x + 0.001f * g0 * g0;
            float nv1 = 0.999f * v2.y + 0.001f * g1 * g1;
            *(float2*)(Mm + id) = make_float2(nm0, nm1);
            *(float2*)(Vv + id) = make_float2(nv0, nv1);
            float2 z2 = *(const float2*)(Z + id);
            z2.x -= 0.01f * (nm0 * bc1) / (sqrtf(nv0 * bc2) + 1e-8f);
            z2.y -= 0.01f * (nm1 * bc1) / (sqrtf(nv1 * bc2) + 1e-8f);
            *(float2*)(Z + id) = z2;
            *(__half2*)(Zq + id) = __floats2half2_rn(z2.x * ISCL, z2.y * ISCL);
        }
    }
}

// ---------------------------------------------------------------------------
// Host driver
// ---------------------------------------------------------------------------
extern "C" void kernel_launch(void* const* d_in, const int* in_sizes, int n_in,
                              void* d_out, int out_size)
{
    (void)in_sizes; (void)n_in; (void)out_size;
    const float* x      = (const float*)d_in[0];
    const float* u      = (const float*)d_in[1];
    const float* W_in   = (const float*)d_in[2];
    const float* b_in   = (const float*)d_in[3];
    const float* Wzs    = (const float*)d_in[4];
    const float* Wxs    = (const float*)d_in[5];
    const float* bs     = (const float*)d_in[6];
    const float* wz_out = (const float*)d_in[7];
    const float* wx_out = (const float*)d_in[8];
    float* z = (float*)d_out;

    float* buf = nullptr;
    { void* p = nullptr; cudaGetSymbolAddress(&p, g_buf); buf = (float*)p; }
    __half* hb = nullptr;
    { void* p = nullptr; cudaGetSymbolAddress(&p, g_hf); hb = (__half*)p; }

    float* C = buf + O_C;

    static bool attr_done = false;
    if (!attr_done) {
        cudaFuncSetAttribute(kfwd<0>, cudaFuncAttributeMaxDynamicSharedMemorySize, SMEM_BYTES);
        cudaFuncSetAttribute(kfwd<1>, cudaFuncAttributeMaxDynamicSharedMemorySize, SMEM_BYTES);
        cudaFuncSetAttribute(kfwd<2>, cudaFuncAttributeMaxDynamicSharedMemorySize, SMEM_BYTES);
        cudaFuncSetAttribute(kbwd<true>,  cudaFuncAttributeMaxDynamicSharedMemorySize, SMEM_BYTES);
        cudaFuncSetAttribute(kbwd<false>, cudaFuncAttributeMaxDynamicSharedMemorySize, SMEM_BYTES);
        cudaFuncSetAttribute(kbwdin, cudaFuncAttributeMaxDynamicSharedMemorySize, SMEM_BYTES);
        attr_done = true;
    }

    kprep<<<2048, 512>>>(Wzs, wz_out, W_in, Wxs, z);
    kpre<<<dim3(Hd / BN, Bsz / BM, 4), NTHR>>>(x, u, W_in, b_in, Wxs, bs);

    const dim3 gF(Hd / BN, Bsz / BM);            // 13 x 32
    const dim3 gB((Hd + Zd) / BN, Bsz / BM);     // 17 x 32
    const dim3 gI(Zd / BN, Bsz / BM);            // 4 x 32
    const dim3 blk(NTHR);

    __half *Zq = hb + OB_Z;
    __half *DA = hb + OB_DA, *DB = hb + OB_DB;

    // Gradient scale plan (powers of 2, exact): s3=1, s2=1, s1=2^-4, s0=2^-13
    const float RS_32 = 1.0f;
    const float RS_21 = 0.0625f;            // 2^-4
    const float RS_10 = 0.001953125f;       // 2^-9
    const float GS_3  = 0.03125f;           // 2^-5
    const float GS_2  = 0.03125f;           // 2^-5
    const float GS_1  = 0.5f;               // 2^-1
    const float GS_0  = 256.0f;             // 2^8

    for (int t = 0; t < NSTEPS; t++) {
        kfwd<0><<<gF, blk, SMEM_BYTES>>>(
            Zq, hb + OB_WINZ,
            (const __half*)nullptr, (const __half*)nullptr,
            C, hb + OB_H);
        for (int l = 0; l < 3; l++) {
            __half* Ain = hb + OB_H + (size_t)l * BH;
            __half* Out = (l < 2) ? hb + OB_H + (size_t)(l + 1) * BH : DA;
            if (l < 2)
                kfwd<1><<<gF, blk, SMEM_BYTES>>>(
                    Ain, hb + OB_SWZF + (size_t)l * HH,
                    Zq, hb + OB_WXZ + (size_t)l * (Hd * Zd),
                    C + (size_t)(l + 1) * BH, Out);
            else
                kfwd<2><<<gF, blk, SMEM_BYTES>>>(
                    Ain, hb + OB_SWZF + (size_t)l * HH,
                    Zq, hb + OB_WXZ + (size_t)l * (Hd * Zd),
                    C + (size_t)(l + 1) * BH, Out);
        }
        kbwd<true><<<gB, blk, SMEM_BYTES>>>(
            DA, hb + OB_SWZT + 2ull * HH, hb + OB_WXZT + 2ull * (Zd * Hd),
            hb + OB_H + 2ull * BH, DB, wx_out, RS_32, GS_3);
        kbwd<false><<<gB, blk, SMEM_BYTES>>>(
            DB, hb + OB_SWZT + 1ull * HH, hb + OB_WXZT + 1ull * (Zd * Hd),
            hb + OB_H + 1ull * BH, DA, wx_out, RS_21, GS_2);
        kbwd<false><<<gB, blk, SMEM_BYTES>>>(
            DA, hb + OB_SWZT, hb + OB_WXZT,
            hb + OB_H, DB, wx_out, RS_10, GS_1);
        double p1 = 1.0, p2 = 1.0;
        for (int q = 0; q <= t; q++) { p1 *= 0.9; p2 *= 0.999; }
        float bc1 = (float)(1.0 / (1.0 - p1));
        float bc2 = (float)(1.0 / (1.0 - p2));
        kbwdin<<<gI, blk, SMEM_BYTES>>>(
            DB, hb + OB_WINZT, z, Zq, bc1, bc2, GS_0);
    }
}

// round 13
// speedup vs baseline: 2.3885x; 1.0963x over previous
#include <cuda_runtime.h>
#include <cuda_fp16.h>
#include <math.h>
#include <stdint.h>

// ---------------------------------------------------------------------------
// KoopmanPhiICNN encode, R13: single-pass fp16 mma.sync GEMMs, BKT=64
// (half the pipeline stages/barriers of R12). Exact power-of-2 scaling:
// activations x2^-5, weights x2^5, gradient scales s3=1,s2=1,s1=2^-4,s0=2^-13.
// 3-stage cp.async pipeline, 256 thr, 32x32 warp tile.
// ---------------------------------------------------------------------------

#define Bsz 4096
#define Hd  832
#define Zd  256
#define BH  (Bsz*Hd)
#define HH  (Hd*Hd)
#define BZ  (Bsz*Zd)
#define NSTEPS 64

#define BM 128
#define BN 64
#define BKT 64
#define BK 16
#define NTHR 256
#define NSTAGE 3

#define SCL   32.0f      // weight pre-scale (2^5)
#define ISCL  0.03125f   // activation store scale (2^-5)

// ---- fp32 scratch ----
#define O_SWZO 0ull
#define O_C    (O_SWZO + 1024ull)
#define O_G    (O_C + 4ull*BH)
#define O_M    (O_G + (unsigned long long)BZ)
#define O_V    (O_M + (unsigned long long)BZ)
#define TOTALF (O_V + (unsigned long long)BZ)
__device__ __align__(16) float g_buf[TOTALF];

// ---- fp16 scratch ----
#define SZ_WINZ  (832ull*256ull)
#define SZ_WXZ   (3ull*832ull*256ull)
#define SZ_SWZ   (3ull*(unsigned long long)HH)
#define OB_WINZ   0ull
#define OB_WXZ    (OB_WINZ + SZ_WINZ)
#define OB_SWZF   (OB_WXZ + SZ_WXZ)
#define OB_SWZT   (OB_SWZF + SZ_SWZ)
#define OB_WXZT   (OB_SWZT + SZ_SWZ)
#define OB_WINZT  (OB_WXZT + SZ_WXZ)
#define OB_H      (OB_WINZT + SZ_WINZ)
#define OB_DA     (OB_H + 3ull*BH)
#define OB_DB     (OB_DA + (unsigned long long)BH)
#define OB_Z      (OB_DB + (unsigned long long)BH)
#define TOTALH    (OB_Z + (unsigned long long)BZ)
__device__ __align__(16) __half g_hf[TOTALH];

__device__ __forceinline__ float sp_(float x) {
    return fmaxf(x, 0.f) + log1pf(expf(-fabsf(x)));
}
__device__ __forceinline__ float sig_(float x) { return 1.f / (1.f + expf(-x)); }
__device__ __forceinline__ float sig_from_h(float h) { return -expm1f(-h); }

// ---------------------------------------------------------------------------
// TN tensor-core GEMM core: C[128,64] += A[128,K]*B[64,K]^T, single fp16,
// K-stage = 64 (rows of 64 halves, stride SA=72 -> conflict-free ldsm).
// ---------------------------------------------------------------------------
#define SA 72
#define OFF_A  0
#define OFF_B  (128*SA)
#define STAGE_H ((128+64)*SA)               // 13824 halves = 27648 B
#define SMEM_BYTES (NSTAGE*2*STAGE_H)       // 82944 B

__device__ __forceinline__ void ldsm4(uint32_t* r, uint32_t addr) {
    asm volatile("ldmatrix.sync.aligned.m8n8.x4.shared.b16 {%0,%1,%2,%3}, [%4];\n"
        : "=r"(r[0]), "=r"(r[1]), "=r"(r[2]), "=r"(r[3]) : "r"(addr));
}
__device__ __forceinline__ void mmah(float* c, const uint32_t* a, uint32_t b0, uint32_t b1) {
    asm volatile("mma.sync.aligned.m16n8k16.row.col.f32.f16.f16.f32 "
        "{%0,%1,%2,%3},{%4,%5,%6,%7},{%8,%9},{%0,%1,%2,%3};\n"
        : "+f"(c[0]), "+f"(c[1]), "+f"(c[2]), "+f"(c[3])
        : "r"(a[0]), "r"(a[1]), "r"(a[2]), "r"(a[3]), "r"(b0), "r"(b1));
}
__device__ __forceinline__ void cp16(uint32_t dst, const void* src) {
    asm volatile("cp.async.cg.shared.global [%0], [%1], 16;\n" :: "r"(dst), "l"(src));
}
__device__ __forceinline__ void cpcommit() { asm volatile("cp.async.commit_group;\n"); }
template<int N> __device__ __forceinline__ void cpwait() {
    asm volatile("cp.async.wait_group %0;\n" :: "n"(N));
}

__device__ __forceinline__ void ld_stage(uint32_t smst,
    const __half* __restrict__ A, int lda,
    const __half* __restrict__ B, int ldb,
    int m0, int n0, int k0, int tid)
{
    // A: 128 rows x 8 k-chunks(16B) = 1024 chunks, 4 per thread
#pragma unroll
    for (int h = 0; h < 4; h++) {
        int ch = tid + h * 256;
        int row = ch >> 3, kc = ch & 7;
        size_t go = (size_t)(m0 + row) * lda + k0 + kc * 8;
        uint32_t so = smst + 2 * (OFF_A + row * SA + kc * 8);
        cp16(so, A + go);
    }
    // B: 64 rows x 8 chunks = 512, 2 per thread
#pragma unroll
    for (int h = 0; h < 2; h++) {
        int ch = tid + h * 256;
        int row = ch >> 3, kc = ch & 7;
        size_t go = (size_t)(n0 + row) * ldb + k0 + kc * 8;
        uint32_t so = smst + 2 * (OFF_B + row * SA + kc * 8);
        cp16(so, B + go);
    }
}

__device__ __forceinline__ void compute_stage(float acc[2][4][4], uint32_t smst,
                                              int lane, int wm, int wn)
{
#pragma unroll
    for (int kk = 0; kk < 4; kk++) {
        const int k16 = kk * 16;
        uint32_t a0[4], a1[4];
        {
            int arow = lane & 15;
            int akoff = k16 + ((lane >> 4) << 3);
            uint32_t ad = smst + 2 * ((wm + arow) * SA + akoff);
            ldsm4(a0, ad);
            ldsm4(a1, ad + 2 * 16 * SA);
        }
        uint32_t b0[4], b1[4];
        {
            int brow = ((lane >> 4) << 3) + (lane & 7);
            int bkoff = k16 + (((lane >> 3) & 1) << 3);
            uint32_t bd = smst + 2 * (OFF_B + (wn + brow) * SA + bkoff);
            ldsm4(b0, bd);
            ldsm4(b1, bd + 2 * 16 * SA);
        }
#pragma unroll
        for (int mi = 0; mi < 2; mi++) {
            const uint32_t* Af = mi ? a1 : a0;
#pragma unroll
            for (int ni = 0; ni < 4; ni++) {
                const uint32_t* Bf = (ni < 2) ? b0 : b1;
                int h2 = (ni & 1) * 2;
                mmah(acc[mi][ni], Af, Bf[h2], Bf[h2 + 1]);
            }
        }
    }
}

// 3-stage pipeline: one barrier per stage, loads after compute.
__device__ __forceinline__ void gemm_tn(float acc[2][4][4], uint32_t smbase,
    const __half* A, int lda,
    const __half* B, int ldb,
    int kt, int m0, int n0, int tid, int lane, int wm, int wn)
{
    __syncthreads();   // previous users of smem done
    ld_stage(smbase, A, lda, B, ldb, m0, n0, 0, tid);
    cpcommit();
    if (kt > 1) ld_stage(smbase + 2 * STAGE_H, A, lda, B, ldb, m0, n0, BKT, tid);
    cpcommit();

    for (int t = 0; t < kt; t++) {
        cpwait<1>();
        __syncthreads();
        compute_stage(acc, smbase + (t % 3) * 2 * STAGE_H, lane, wm, wn);
        if (t + 2 < kt)
            ld_stage(smbase + ((t + 2) % 3) * 2 * STAGE_H,
                     A, lda, B, ldb, m0, n0, (t + 2) * BKT, tid);
        cpcommit();
    }
    cpwait<0>();
}

// ---------------------------------------------------------------------------
// fp32 SIMT kpre (runs once): c[s] = [x|u] @ W_s[:,256:]^T + bias_s
// ---------------------------------------------------------------------------
__device__ __forceinline__ void mm_compute(float acc[8][4],
    const float As[BK][BM + 4], const float Bs[BK][BN], int tx, int ty)
{
#pragma unroll
    for (int kk = 0; kk < BK; kk++) {
        float4 a0 = *reinterpret_cast<const float4*>(&As[kk][ty * 8]);
        float4 a1 = *reinterpret_cast<const float4*>(&As[kk][ty * 8 + 4]);
        float4 b  = *reinterpret_cast<const float4*>(&Bs[kk][tx * 4]);
        float av[8] = {a0.x, a0.y, a0.z, a0.w, a1.x, a1.y, a1.z, a1.w};
        float bv[4] = {b.x, b.y, b.z, b.w};
#pragma unroll
        for (int i = 0; i < 8; i++)
#pragma unroll
            for (int j = 0; j < 4; j++)
                acc[i][j] = fmaf(av[i], bv[j], acc[i][j]);
    }
}
__device__ __forceinline__ void st_nt(float As[BK][BM + 4], float Bs[BK][BN],
                                      int r, int c, float4 va0, float4 va1, float4 vb)
{
    As[c + 0][r] = va0.x; As[c + 1][r] = va0.y; As[c + 2][r] = va0.z; As[c + 3][r] = va0.w;
    As[c + 0][r + 64] = va1.x; As[c + 1][r + 64] = va1.y; As[c + 2][r + 64] = va1.z; As[c + 3][r + 64] = va1.w;
    Bs[c + 0][r] = vb.x; Bs[c + 1][r] = vb.y; Bs[c + 2][r] = vb.z; Bs[c + 3][r] = vb.w;
}

__global__ void __launch_bounds__(NTHR) kpre(
    const float* __restrict__ x, const float* __restrict__ u,
    const float* __restrict__ W_in, const float* __restrict__ b_in,
    const float* __restrict__ Wxs, const float* __restrict__ bs)
{
    __shared__ float As[2][BK][BM + 4];
    __shared__ float Bs[2][BK][BN];
    const int tid = threadIdx.x, tx = tid & 15, ty = tid >> 4;
    const int m0 = blockIdx.y * BM, n0 = blockIdx.x * BN;
    const int s = blockIdx.z;
    const float* W    = (s == 0) ? W_in : Wxs + (size_t)(s - 1) * HH;
    const float* bias = (s == 0) ? b_in : bs + (size_t)(s - 1) * Hd;
    float* Out = g_buf + O_C + (size_t)s * BH;

    float acc[8][4];
#pragma unroll
    for (int i = 0; i < 8; i++)
#pragma unroll
        for (int j = 0; j < 4; j++) acc[i][j] = 0.f;

    const int r = tid >> 2;
    const int c = (tid & 3) * 4;
    const int kt = 576 / BK;
    const float* Bp = W + (size_t)(n0 + r) * Hd + 256 + c;

    float4 va0, va1, vb;
    va0 = *reinterpret_cast<const float4*>(&x[(size_t)(m0 + r) * 512 + c]);
    va1 = *reinterpret_cast<const float4*>(&x[(size_t)(m0 + r + 64) * 512 + c]);
    vb  = *reinterpret_cast<const float4*>(Bp);
    __syncthreads();
    st_nt(As[0], Bs[0], r, c, va0, va1, vb);
    __syncthreads();

    for (int t = 0; t < kt; t++) {
        int buf = t & 1;
        if (t + 1 < kt) {
            int k = (t + 1) * BK + c;
            if (k < 512) {
                va0 = *reinterpret_cast<const float4*>(&x[(size_t)(m0 + r) * 512 + k]);
                va1 = *reinterpret_cast<const float4*>(&x[(size_t)(m0 + r + 64) * 512 + k]);
            } else {
                va0 = *reinterpret_cast<const float4*>(&u[(size_t)(m0 + r) * 64 + (k - 512)]);
                va1 = *reinterpret_cast<const float4*>(&u[(size_t)(m0 + r + 64) * 64 + (k - 512)]);
            }
            vb = *reinterpret_cast<const float4*>(Bp + (t + 1) * BK);
        }
        mm_compute(acc, As[buf], Bs[buf], tx, ty);
        if (t + 1 < kt) st_nt(As[buf ^ 1], Bs[buf ^ 1], r, c, va0, va1, vb);
        __syncthreads();
    }

    const float4 b4 = *reinterpret_cast<const float4*>(&bias[n0 + tx * 4]);
#pragma unroll
    for (int i = 0; i < 8; i++) {
        int m = m0 + ty * 8 + i;
        float4 o;
        o.x = acc[i][0] + b4.x; o.y = acc[i][1] + b4.y;
        o.z = acc[i][2] + b4.z; o.w = acc[i][3] + b4.w;
        *reinterpret_cast<float4*>(&Out[(size_t)m * Hd + n0 + tx * 4]) = o;
    }
}

// ---------------------------------------------------------------------------
// Prep: scaled single-fp16 weight copies/transposes + state init
// ---------------------------------------------------------------------------
__global__ void kprep(const float* __restrict__ Wzs, const float* __restrict__ wz_out,
                      const float* __restrict__ W_in, const float* __restrict__ Wxs,
                      float* __restrict__ Z)
{
    __half* hf = g_hf;
    float* SWZO = g_buf + O_SWZO;
    float* Mm = g_buf + O_M;
    float* Vv = g_buf + O_V;
    const int n = 3 * HH;
    for (int i = blockIdx.x * blockDim.x + threadIdx.x; i < n;
         i += gridDim.x * blockDim.x) {
        int l = i / HH, o = i - l * HH;
        int r = o / Hd, c = o - r * Hd;
        float w = sp_(Wzs[i]);
        hf[OB_SWZF + i] = __float2half_rn(w * SCL);
        size_t ti = (size_t)l * HH + (size_t)c * Hd + r;
        hf[OB_SWZT + ti] = __float2half_rn(w);
        if (c < Zd) {
            float wx = Wxs[i] * SCL;
            size_t zi = (size_t)l * (Hd * Zd) + (size_t)r * Zd + c;
            hf[OB_WXZ + zi] = __float2half_rn(wx);
            size_t zt = (size_t)l * (Zd * Hd) + (size_t)c * Hd + r;
            hf[OB_WXZT + zt] = __float2half_rn(wx);
            if (l == 0) {
                float wi = W_in[o] * SCL;
                hf[OB_WINZ + (size_t)r * Zd + c] = __float2half_rn(wi);
                hf[OB_WINZT + (size_t)c * Hd + r] = __float2half_rn(wi);
            }
        }
        if (i < Hd) SWZO[i] = sp_(wz_out[i]);
        if (i < BZ) {
            Z[i] = 0.f; Mm[i] = 0.f; Vv[i] = 0.f;
            hf[OB_Z + i] = __float2half_rn(0.f);
        }
    }
}

// ---------------------------------------------------------------------------
// Forward: MODE 0 input layer, MODE 1 hidden (store h x2^-5),
//          MODE 2 hidden+final (store d3 unscaled).
// ---------------------------------------------------------------------------
template<int MODE>
__global__ void __launch_bounds__(NTHR, 2) kfwd(
    const __half* __restrict__ A1, const __half* __restrict__ B1,
    const __half* __restrict__ A2, const __half* __restrict__ B2,
    const float* __restrict__ C0, __half* __restrict__ O)
{
    extern __shared__ __align__(16) char dsm[];
    uint32_t smbase = (uint32_t)__cvta_generic_to_shared(dsm);
    const int tid = threadIdx.x, lane = tid & 31, wid = tid >> 5;
    const int wm = (wid >> 1) * 32, wn = (wid & 1) * 32;
    const int m0 = blockIdx.y * BM, n0 = blockIdx.x * BN;

    float acc[2][4][4];
#pragma unroll
    for (int a = 0; a < 2; a++)
#pragma unroll
        for (int b = 0; b < 4; b++)
#pragma unroll
            for (int d = 0; d < 4; d++) acc[a][b][d] = 0.f;

    if (MODE == 0) {
        gemm_tn(acc, smbase, A1, Zd, B1, Zd, Zd / BKT, m0, n0, tid, lane, wm, wn);
    } else {
        gemm_tn(acc, smbase, A1, Hd, B1, Hd, Hd / BKT, m0, n0, tid, lane, wm, wn);
        gemm_tn(acc, smbase, A2, Zd, B2, Zd, Zd / BKT, m0, n0, tid, lane, wm, wn);
    }

    const int l4 = lane >> 2, l2 = (lane & 3) * 2;
#pragma unroll
    for (int mi = 0; mi < 2; mi++)
#pragma unroll
    for (int ni = 0; ni < 4; ni++) {
        int mA = m0 + wm + mi * 16 + l4;
        int n  = n0 + wn + ni * 8 + l2;
        size_t iA = (size_t)mA * Hd + n, iB = iA + 8ull * Hd;
        float2 cA = *(const float2*)(C0 + iA);
        float2 cB = *(const float2*)(C0 + iB);
        float v0 = acc[mi][ni][0] + cA.x, v1 = acc[mi][ni][1] + cA.y;
        float v2 = acc[mi][ni][2] + cB.x, v3 = acc[mi][ni][3] + cB.y;
        if (MODE == 2) {
            const float* SWZO = g_buf + O_SWZO;
            float2 s2 = *(const float2*)(SWZO + n);
            v0 = s2.x * sig_(v0); v1 = s2.y * sig_(v1);
            v2 = s2.x * sig_(v2); v3 = s2.y * sig_(v3);
            *(__half2*)(O + iA) = __floats2half2_rn(v0, v1);
            *(__half2*)(O + iB) = __floats2half2_rn(v2, v3);
        } else {
            v0 = sp_(v0); v1 = sp_(v1); v2 = sp_(v2); v3 = sp_(v3);
            *(__half2*)(O + iA) = __floats2half2_rn(v0 * ISCL, v1 * ISCL);
            *(__half2*)(O + iB) = __floats2half2_rn(v2 * ISCL, v3 * ISCL);
        }
    }
}

// ---------------------------------------------------------------------------
// Backward hidden layer.
//  d-path (n<832):  stored_dnext = (acc * sigma') * rs
//  g-path (n>=832): G += acc * gs     (FIRSTG: G = wx_out + acc*gs)
// ---------------------------------------------------------------------------
template<bool FIRSTG>
__global__ void __launch_bounds__(NTHR, 2) kbwd(
    const __half* __restrict__ D,
    const __half* __restrict__ ST, const __half* __restrict__ XT,
    const __half* __restrict__ Hp, __half* __restrict__ O,
    const float* __restrict__ wx_out, float rs, float gs)
{
    extern __shared__ __align__(16) char dsm[];
    uint32_t smbase = (uint32_t)__cvta_generic_to_shared(dsm);
    const int tid = threadIdx.x, lane = tid & 31, wid = tid >> 5;
    const int wm = (wid >> 1) * 32, wn = (wid & 1) * 32;
    const int m0 = blockIdx.y * BM, n0 = blockIdx.x * BN;
    const bool gpath = (n0 >= Hd);
    const int nb = gpath ? (n0 - Hd) : n0;

    float acc[2][4][4];
#pragma unroll
    for (int a = 0; a < 2; a++)
#pragma unroll
        for (int b = 0; b < 4; b++)
#pragma unroll
            for (int d = 0; d < 4; d++) acc[a][b][d] = 0.f;

    gemm_tn(acc, smbase, D, Hd, gpath ? XT : ST, Hd, Hd / BKT,
            m0, nb, tid, lane, wm, wn);

    const int l4 = lane >> 2, l2 = (lane & 3) * 2;
    if (!gpath) {
#pragma unroll
        for (int mi = 0; mi < 2; mi++)
#pragma unroll
        for (int ni = 0; ni < 4; ni++) {
            int mA = m0 + wm + mi * 16 + l4;
            int n  = n0 + wn + ni * 8 + l2;
            size_t iA = (size_t)mA * Hd + n, iB = iA + 8ull * Hd;
            __half2 hA = *(const __half2*)(Hp + iA);
            __half2 hB = *(const __half2*)(Hp + iB);
            float d0 = acc[mi][ni][0] * sig_from_h(__half2float(hA.x) * SCL) * rs;
            float d1 = acc[mi][ni][1] * sig_from_h(__half2float(hA.y) * SCL) * rs;
            float d2 = acc[mi][ni][2] * sig_from_h(__half2float(hB.x) * SCL) * rs;
            float d3 = acc[mi][ni][3] * sig_from_h(__half2float(hB.y) * SCL) * rs;
            *(__half2*)(O + iA) = __floats2half2_rn(d0, d1);
            *(__half2*)(O + iB) = __floats2half2_rn(d2, d3);
        }
    } else {
        float* G = g_buf + O_G;
#pragma unroll
        for (int mi = 0; mi < 2; mi++)
#pragma unroll
        for (int ni = 0; ni < 4; ni++) {
            int mA = m0 + wm + mi * 16 + l4;
            int np = nb + wn + ni * 8 + l2;
            size_t gA = (size_t)mA * Zd + np, gB = gA + 8ull * Zd;
            float2 bA, bB;
            if (FIRSTG) {
                float2 w2 = *(const float2*)(wx_out + np);
                bA = w2; bB = w2;
            } else {
                bA = *(const float2*)(G + gA);
                bB = *(const float2*)(G + gB);
            }
            float2 oA, oB;
            oA.x = bA.x + acc[mi][ni][0] * gs; oA.y = bA.y + acc[mi][ni][1] * gs;
            oB.x = bB.x + acc[mi][ni][2] * gs; oB.y = bB.y + acc[mi][ni][3] * gs;
            *(float2*)(G + gA) = oA;
            *(float2*)(G + gB) = oB;
        }
    }
}

// ---------------------------------------------------------------------------
// Final backward + Adam: g = G + acc*gs; z fp32 master + fp16 copy x2^-5.
// ---------------------------------------------------------------------------
__global__ void __launch_bounds__(NTHR, 2) kbwdin(
    const __half* __restrict__ D, const __half* __restrict__ WT,
    float* __restrict__ Z, __half* __restrict__ Zq,
    float bc1, float bc2, float gs)
{
    extern __shared__ __align__(16) char dsm[];
    uint32_t smbase = (uint32_t)__cvta_generic_to_shared(dsm);
    const int tid = threadIdx.x, lane = tid & 31, wid = tid >> 5;
    const int wm = (wid >> 1) * 32, wn = (wid & 1) * 32;
    const int m0 = blockIdx.y * BM, n0 = blockIdx.x * BN;

    float acc[2][4][4];
#pragma unroll
    for (int a = 0; a < 2; a++)
#pragma unroll
        for (int b = 0; b < 4; b++)
#pragma unroll
            for (int d = 0; d < 4; d++) acc[a][b][d] = 0.f;

    gemm_tn(acc, smbase, D, Hd, WT, Hd, Hd / BKT, m0, n0, tid, lane, wm, wn);

    const float* G = g_buf + O_G;
    float* Mm = g_buf + O_M;
    float* Vv = g_buf + O_V;
    const int l4 = lane >> 2, l2 = (lane & 3) * 2;
#pragma unroll
    for (int mi = 0; mi < 2; mi++)
#pragma unroll
    for (int ni = 0; ni < 4; ni++) {
        int mA = m0 + wm + mi * 16 + l4;
        int np = n0 + wn + ni * 8 + l2;
        size_t idx[2];
        idx[0] = (size_t)mA * Zd + np;
        idx[1] = idx[0] + 8ull * Zd;
#pragma unroll
        for (int hh = 0; hh < 2; hh++) {
            size_t id = idx[hh];
            float g0 = G[id]     + acc[mi][ni][hh * 2 + 0] * gs;
            float g1 = G[id + 1] + acc[mi][ni][hh * 2 + 1] * gs;
            float2 m2 = *(const float2*)(Mm + id);
            float2 v2 = *(const float2*)(Vv + id);
            float nm0 = 0.9f * m2.x + 0.1f * g0;
            float nm1 = 0.9f * m2.y + 0.1f * g1;
            float nv0 = 0.999f * v2.x + 0.001f * g0 * g0;
            float nv1 = 0.999f * v2.y + 0.001f * g1 * g1;
            *(float2*)(Mm + id) = make_float2(nm0, nm1);
            *(float2*)(Vv + id) = make_float2(nv0, nv1);
            float2 z2 = *(const float2*)(Z + id);
            z2.x -= 0.01f * (nm0 * bc1) / (sqrtf(nv0 * bc2) + 1e-8f);
            z2.y -= 0.01f * (nm1 * bc1) / (sqrtf(nv1 * bc2) + 1e-8f);
            *(float2*)(Z + id) = z2;
            *(__half2*)(Zq + id) = __floats2half2_rn(z2.x * ISCL, z2.y * ISCL);
        }
    }
}

// ---------------------------------------------------------------------------
// Host driver
// ---------------------------------------------------------------------------
extern "C" void kernel_launch(void* const* d_in, const int* in_sizes, int n_in,
                              void* d_out, int out_size)
{
    (void)in_sizes; (void)n_in; (void)out_size;
    const float* x      = (const float*)d_in[0];
    const float* u      = (const float*)d_in[1];
    const float* W_in   = (const float*)d_in[2];
    const float* b_in   = (const float*)d_in[3];
    const float* Wzs    = (const float*)d_in[4];
    const float* Wxs    = (const float*)d_in[5];
    const float* bs     = (const float*)d_in[6];
    const float* wz_out = (const float*)d_in[7];
    const float* wx_out = (const float*)d_in[8];
    float* z = (float*)d_out;

    float* buf = nullptr;
    { void* p = nullptr; cudaGetSymbolAddress(&p, g_buf); buf = (float*)p; }
    __half* hb = nullptr;
    { void* p = nullptr; cudaGetSymbolAddress(&p, g_hf); hb = (__half*)p; }

    float* C = buf + O_C;

    static bool attr_done = false;
    if (!attr_done) {
        cudaFuncSetAttribute(kfwd<0>, cudaFuncAttributeMaxDynamicSharedMemorySize, SMEM_BYTES);
        cudaFuncSetAttribute(kfwd<1>, cudaFuncAttributeMaxDynamicSharedMemorySize, SMEM_BYTES);
        cudaFuncSetAttribute(kfwd<2>, cudaFuncAttributeMaxDynamicSharedMemorySize, SMEM_BYTES);
        cudaFuncSetAttribute(kbwd<true>,  cudaFuncAttributeMaxDynamicSharedMemorySize, SMEM_BYTES);
        cudaFuncSetAttribute(kbwd<false>, cudaFuncAttributeMaxDynamicSharedMemorySize, SMEM_BYTES);
        cudaFuncSetAttribute(kbwdin, cudaFuncAttributeMaxDynamicSharedMemorySize, SMEM_BYTES);
        attr_done = true;
    }

    kprep<<<2048, 512>>>(Wzs, wz_out, W_in, Wxs, z);
    kpre<<<dim3(Hd / BN, Bsz / BM, 4), NTHR>>>(x, u, W_in, b_in, Wxs, bs);

    const dim3 gF(Hd / BN, Bsz / BM);            // 13 x 32
    const dim3 gB((Hd + Zd) / BN, Bsz / BM);     // 17 x 32
    const dim3 gI(Zd / BN, Bsz / BM);            // 4 x 32
    const dim3 blk(NTHR);

    __half *Zq = hb + OB_Z;
    __half *DA = hb + OB_DA, *DB = hb + OB_DB;

    // Gradient scale plan (powers of 2, exact): s3=1, s2=1, s1=2^-4, s0=2^-13
    const float RS_32 = 1.0f;
    const float RS_21 = 0.0625f;            // 2^-4
    const float RS_10 = 0.001953125f;       // 2^-9
    const float GS_3  = 0.03125f;           // 2^-5
    const float GS_2  = 0.03125f;           // 2^-5
    const float GS_1  = 0.5f;               // 2^-1
    const float GS_0  = 256.0f;             // 2^8

    for (int t = 0; t < NSTEPS; t++) {
        kfwd<0><<<gF, blk, SMEM_BYTES>>>(
            Zq, hb + OB_WINZ,
            (const __half*)nullptr, (const __half*)nullptr,
            C, hb + OB_H);
        for (int l = 0; l < 3; l++) {
            __half* Ain = hb + OB_H + (size_t)l * BH;
            __half* Out = (l < 2) ? hb + OB_H + (size_t)(l + 1) * BH : DA;
            if (l < 2)
                kfwd<1><<<gF, blk, SMEM_BYTES>>>(
                    Ain, hb + OB_SWZF + (size_t)l * HH,
                    Zq, hb + OB_WXZ + (size_t)l * (Hd * Zd),
                    C + (size_t)(l + 1) * BH, Out);
            else
                kfwd<2><<<gF, blk, SMEM_BYTES>>>(
                    Ain, hb + OB_SWZF + (size_t)l * HH,
                    Zq, hb + OB_WXZ + (size_t)l * (Hd * Zd),
                    C + (size_t)(l + 1) * BH, Out);
        }
        kbwd<true><<<gB, blk, SMEM_BYTES>>>(
            DA, hb + OB_SWZT + 2ull * HH, hb + OB_WXZT + 2ull * (Zd * Hd),
            hb + OB_H + 2ull * BH, DB, wx_out, RS_32, GS_3);
        kbwd<false><<<gB, blk, SMEM_BYTES>>>(
            DB, hb + OB_SWZT + 1ull * HH, hb + OB_WXZT + 1ull * (Zd * Hd),
            hb + OB_H + 1ull * BH, DA, wx_out, RS_21, GS_2);
        kbwd<false><<<gB, blk, SMEM_BYTES>>>(
            DA, hb + OB_SWZT, hb + OB_WXZT,
            hb + OB_H, DB, wx_out, RS_10, GS_1);
        double p1 = 1.0, p2 = 1.0;
        for (int q = 0; q <= t; q++) { p1 *= 0.9; p2 *= 0.999; }
        float bc1 = (float)(1.0 / (1.0 - p1));
        float bc2 = (float)(1.0 / (1.0 - p2));
        kbwdin<<<gI, blk, SMEM_BYTES>>>(
            DB, hb + OB_WINZT, z, Zq, bc1, bc2, GS_0);
    }
}